// round 1
// baseline (speedup 1.0000x reference)
#include <cuda_runtime.h>
#include <cstdint>
#include <cstdio>

// Problem shape (fixed per reference)
#define B_  16
#define N_  1024
#define D_  768
#define H_  12
#define HS_ 64
#define M_  (B_*N_)   // 16384 token rows
#define L_  2
#define EPS_ 1e-6f

// ---------------------------------------------------------------------------
// Scratch (no allocation allowed -> __device__ globals)
// ---------------------------------------------------------------------------
__device__ float g_xn[M_*D_];   // layernorm(x)
__device__ float g_wv[D_*D_];   // Wv packed [d][h*HS+k]
__device__ float g_v [M_*D_];   // v_cat[(b*N+n)][h*HS+k]
__device__ float g_x1[M_*D_];   // x + y (residual)
__device__ float g_t [M_*D_];   // ffn gemm out
__device__ float g_z [M_*D_];   // ffn activation out

// ---------------------------------------------------------------------------
// Pack Wv [H,D,HS] -> g_wv [D, H*HS] row-major
// ---------------------------------------------------------------------------
__global__ void pack_wv_kernel(const float* __restrict__ Wv) {
    int idx = blockIdx.x * blockDim.x + threadIdx.x;
    if (idx >= H_ * D_ * HS_) return;
    int h = idx / (D_ * HS_);
    int r = idx % (D_ * HS_);
    int d = r / HS_;
    int k = r % HS_;
    g_wv[d * D_ + h * HS_ + k] = Wv[idx];
}

// ---------------------------------------------------------------------------
// LayerNorm over D=768 (optionally followed by swish)
// One block per row, 256 threads, 3 elems each
// ---------------------------------------------------------------------------
__global__ void __launch_bounds__(256) ln_kernel(
    const float* __restrict__ in,
    const float* __restrict__ scale,
    const float* __restrict__ bias,
    float* __restrict__ out,
    int do_swish)
{
    int row = blockIdx.x;
    const float* p = in + (size_t)row * D_;
    int t = threadIdx.x;

    float v0 = p[t];
    float v1 = p[t + 256];
    float v2 = p[t + 512];
    float s = v0 + v1 + v2;
    float q = v0*v0 + v1*v1 + v2*v2;

    #pragma unroll
    for (int o = 16; o; o >>= 1) {
        s += __shfl_xor_sync(0xffffffffu, s, o);
        q += __shfl_xor_sync(0xffffffffu, q, o);
    }
    __shared__ float red[16];
    int warp = t >> 5, lane = t & 31;
    if (lane == 0) { red[warp] = s; red[warp + 8] = q; }
    __syncthreads();
    if (t == 0) {
        float a = 0.f, b = 0.f;
        #pragma unroll
        for (int i = 0; i < 8; i++) { a += red[i]; b += red[i + 8]; }
        red[0] = a; red[8] = b;
    }
    __syncthreads();
    float mu  = red[0] * (1.f / D_);
    float var = red[8] * (1.f / D_) - mu * mu;
    float inv = rsqrtf(var + EPS_);

    float* o = out + (size_t)row * D_;
    #pragma unroll
    for (int c = 0; c < 3; c++) {
        int col = t + c * 256;
        float val = (p[col] - mu) * inv * scale[col] + bias[col];
        if (do_swish) val = val * (1.f / (1.f + expf(-val)));
        o[col] = val;
    }
}

// ---------------------------------------------------------------------------
// SGEMM: C = A[M,K] @ Bm[K,N] (+ bias[N]).  M%128==0, N%128==0, K%16==0
// 128x128 tile, BK=16, 256 threads, 8x8 per thread
// ---------------------------------------------------------------------------
#define BM 128
#define BN 128
#define BK 16
#define TM 8
#define TN 8

__global__ void __launch_bounds__(256) sgemm_kernel(
    const float* __restrict__ A,
    const float* __restrict__ Bm,
    const float* __restrict__ bias,   // may be null
    float* __restrict__ C,
    int Mdim, int Ndim, int Kdim)
{
    __shared__ float As[BK][BM];
    __shared__ float Bs[BK][BN];

    int tid = threadIdx.x;
    int ty = tid / (BN / TN);   // 0..15
    int tx = tid % (BN / TN);   // 0..15

    const float* Ablk = A  + (size_t)blockIdx.y * BM * Kdim;
    const float* Bblk = Bm + (size_t)blockIdx.x * BN;

    int aRow = tid / (BK / 4);        // 0..63
    int aCol = (tid % (BK / 4)) * 4;  // 0,4,8,12
    int bRow = tid / (BN / 4);        // 0..7
    int bCol = (tid % (BN / 4)) * 4;  // 0..124

    float acc[TM][TN] = {};
    float ra[TM], rb[TN];

    for (int k0 = 0; k0 < Kdim; k0 += BK) {
        #pragma unroll
        for (int r = 0; r < BM; r += 64) {
            float4 v = *reinterpret_cast<const float4*>(
                Ablk + (size_t)(aRow + r) * Kdim + k0 + aCol);
            As[aCol + 0][aRow + r] = v.x;
            As[aCol + 1][aRow + r] = v.y;
            As[aCol + 2][aRow + r] = v.z;
            As[aCol + 3][aRow + r] = v.w;
        }
        #pragma unroll
        for (int r = 0; r < BK; r += 8) {
            float4 v = *reinterpret_cast<const float4*>(
                Bblk + (size_t)(k0 + bRow + r) * Ndim + bCol);
            *reinterpret_cast<float4*>(&Bs[bRow + r][bCol]) = v;
        }
        __syncthreads();

        #pragma unroll
        for (int k = 0; k < BK; k++) {
            #pragma unroll
            for (int i = 0; i < TM; i++) ra[i] = As[k][ty * TM + i];
            #pragma unroll
            for (int j = 0; j < TN; j++) rb[j] = Bs[k][tx * TN + j];
            #pragma unroll
            for (int i = 0; i < TM; i++)
                #pragma unroll
                for (int j = 0; j < TN; j++)
                    acc[i][j] += ra[i] * rb[j];
        }
        __syncthreads();
    }

    #pragma unroll
    for (int i = 0; i < TM; i++) {
        int row = blockIdx.y * BM + ty * TM + i;
        #pragma unroll
        for (int j = 0; j < TN; j++) {
            int col = blockIdx.x * BN + tx * TN + j;
            float c = acc[i][j];
            if (bias) c += bias[col];
            C[(size_t)row * Ndim + col] = c;
        }
    }
}

// ---------------------------------------------------------------------------
// Circulant mixing + residual:
//   x1[(b*N+i), h*HS+k] = x[...] + sum_j alpha[h,(i-j)%N] * v[(b*N+j), h*HS+k]
// Block: 128 rows(i) x 64 cols(k), BK=32 over j, 128 threads, 8x8 per thread
// alpha[h] held in smem duplicated x2 to avoid the mod.
// ---------------------------------------------------------------------------
__global__ void __launch_bounds__(128) circulant_kernel(
    const float* __restrict__ alpha,
    const float* __restrict__ x)
{
    __shared__ float sAlpha[2 * N_ > 2048 ? 2 * N_ : 2048]; // 2048 floats
    __shared__ float Bs[32][HS_];

    int tid = threadIdx.x;
    int bh = blockIdx.y;
    int b = bh / H_;
    int h = bh % H_;
    int iBase = blockIdx.x * 128;

    const float* alphah = alpha + (size_t)h * N_;
    for (int t = tid; t < 2 * N_; t += 128)
        sAlpha[t] = alphah[t & (N_ - 1)];

    int tx = tid % 8;    // col group (8 cols each)
    int ty = tid / 8;    // row group (8 rows each), 0..15
    int bRow = tid / 16;        // 0..7
    int bCol = (tid % 16) * 4;  // 0..60

    float acc[8][8] = {};
    float ra[8], rb[8];

    __syncthreads();

    for (int k0 = 0; k0 < N_; k0 += 32) {
        #pragma unroll
        for (int r = 0; r < 4; r++) {
            int j = bRow + 8 * r;
            float4 vv = *reinterpret_cast<const float4*>(
                g_v + (size_t)(b * N_ + k0 + j) * D_ + h * HS_ + bCol);
            *reinterpret_cast<float4*>(&Bs[j][bCol]) = vv;
        }
        __syncthreads();

        #pragma unroll 8
        for (int j = 0; j < 32; j++) {
            int base = iBase + ty * 8 - (k0 + j) + N_;   // in [1, 2047]
            #pragma unroll
            for (int i = 0; i < 8; i++) ra[i] = sAlpha[base + i];
            float4 rb0 = *reinterpret_cast<float4*>(&Bs[j][tx * 8]);
            float4 rb1 = *reinterpret_cast<float4*>(&Bs[j][tx * 8 + 4]);
            rb[0]=rb0.x; rb[1]=rb0.y; rb[2]=rb0.z; rb[3]=rb0.w;
            rb[4]=rb1.x; rb[5]=rb1.y; rb[6]=rb1.z; rb[7]=rb1.w;
            #pragma unroll
            for (int i = 0; i < 8; i++)
                #pragma unroll
                for (int jj = 0; jj < 8; jj++)
                    acc[i][jj] += ra[i] * rb[jj];
        }
        __syncthreads();
    }

    #pragma unroll
    for (int i = 0; i < 8; i++) {
        int row = b * N_ + iBase + ty * 8 + i;
        #pragma unroll
        for (int jj = 0; jj < 8; jj++) {
            int col = h * HS_ + tx * 8 + jj;
            g_x1[(size_t)row * D_ + col] =
                x[(size_t)row * D_ + col] + acc[i][jj];
        }
    }
}

// ---------------------------------------------------------------------------
// Final: out = log_cosh(z + x1)
// ---------------------------------------------------------------------------
__global__ void final_kernel(float* __restrict__ out) {
    int i = blockIdx.x * blockDim.x + threadIdx.x;
    if (i >= M_ * D_) return;
    float s = g_z[i] + g_x1[i];
    float ax = fabsf(s);
    out[i] = ax + log1pf(expf(-2.f * ax)) - 0.69314718055994530942f;
}

// ---------------------------------------------------------------------------
// Launch
// ---------------------------------------------------------------------------
extern "C" void kernel_launch(void* const* d_in, const int* in_sizes, int n_in,
                              void* d_out, int out_size)
{
    const float* x     = (const float*)d_in[0];
    const float* ln1_s = (const float*)d_in[1];
    const float* ln1_b = (const float*)d_in[2];
    const float* Wv    = (const float*)d_in[3];
    const float* alpha = (const float*)d_in[4];
    const float* Wf    = (const float*)d_in[5];
    const float* bf    = (const float*)d_in[6];
    const float* lnf_s = (const float*)d_in[7];
    const float* lnf_b = (const float*)d_in[8];
    float* out = (float*)d_out;

    float *xn, *wv, *v, *x1, *t, *z;
    cudaGetSymbolAddress((void**)&xn, g_xn);
    cudaGetSymbolAddress((void**)&wv, g_wv);
    cudaGetSymbolAddress((void**)&v,  g_v);
    cudaGetSymbolAddress((void**)&x1, g_x1);
    cudaGetSymbolAddress((void**)&t,  g_t);
    cudaGetSymbolAddress((void**)&z,  g_z);

    // 1. pack Wv -> [D, H*HS]
    pack_wv_kernel<<<(H_*D_*HS_ + 255) / 256, 256>>>(Wv);

    // 2. xn = layernorm(x)
    ln_kernel<<<M_, 256>>>(x, ln1_s, ln1_b, xn, 0);

    // 3. v_cat = xn @ wv     [16384,768]@[768,768]
    sgemm_kernel<<<dim3(D_ / BN, M_ / BM), 256>>>(xn, wv, nullptr, v, M_, D_, D_);

    // 4. x1 = x + circulant(alpha) @ v  (per b,h)
    circulant_kernel<<<dim3(N_ / 128, B_ * H_), 128>>>(alpha, x);

    // 5-8. FFN x2: t = z @ Wf[l] + bf[l]; z = swish(layernorm(t))
    const float* zin = x1;
    for (int l = 0; l < L_; l++) {
        sgemm_kernel<<<dim3(D_ / BN, M_ / BM), 256>>>(
            zin, Wf + (size_t)l * D_ * D_, bf + (size_t)l * D_, t, M_, D_, D_);
        ln_kernel<<<M_, 256>>>(t, lnf_s + (size_t)l * D_, lnf_b + (size_t)l * D_, z, 1);
        zin = z;
    }

    // 9. out = log_cosh(z + x1)
    final_kernel<<<(M_ * D_ + 255) / 256, 256>>>(out);
}

// round 3
// speedup vs baseline: 1.8398x; 1.8398x over previous
#include <cuda_runtime.h>
#include <cuda_bf16.h>
#include <cstdint>

// ---------------------------------------------------------------------------
// Problem shape
// ---------------------------------------------------------------------------
#define B_  16
#define N_  1024
#define D_  768
#define H_  12
#define HS_ 64
#define M_  (B_*N_)     // 16384 token rows
#define L_  2
#define EPS_ 1e-6f

// ---------------------------------------------------------------------------
// Scratch
// ---------------------------------------------------------------------------
__device__ __nv_bfloat16 g_xnh[M_*D_], g_xnl[M_*D_];        // LN1(x) split
__device__ __nv_bfloat16 g_wvTh[D_*D_], g_wvTl[D_*D_];      // Wv^T [n=h*64+k][d]
__device__ __nv_bfloat16 g_wfTh[L_*D_*D_], g_wfTl[L_*D_*D_];// Wf^T [l][n][d]
__device__ __nv_bfloat16 g_vch[H_*N_*N_], g_vcl[H_*N_*N_];  // v [h][b*64+k][j]
__device__ __nv_bfloat16 g_cch[H_*N_*N_], g_ccl[H_*N_*N_];  // C [h][i][j]
__device__ float         g_x1 [M_*D_];
__device__ __nv_bfloat16 g_x1h[M_*D_], g_x1l[M_*D_];
__device__ float         g_t  [M_*D_];
__device__ float         g_z  [M_*D_];
__device__ __nv_bfloat16 g_zh [M_*D_], g_zl [M_*D_];

// ---------------------------------------------------------------------------
// Helpers
// ---------------------------------------------------------------------------
__device__ __forceinline__ uint32_t smem_u32(const void* p) {
    uint32_t a;
    asm("{ .reg .u64 t; cvta.to.shared.u64 t, %1; cvt.u32.u64 %0, t; }"
        : "=r"(a) : "l"(p));
    return a;
}
__device__ __forceinline__ void split_store(__nv_bfloat16* ph, __nv_bfloat16* pl,
                                            size_t o, float f) {
    __nv_bfloat16 hi = __float2bfloat16(f);
    ph[o] = hi;
    pl[o] = __float2bfloat16(f - __bfloat162float(hi));
}
__device__ __forceinline__ void ldsm_x4(uint32_t* d, uint32_t addr) {
    asm volatile("ldmatrix.sync.aligned.m8n8.x4.shared.b16 {%0,%1,%2,%3}, [%4];"
                 : "=r"(d[0]), "=r"(d[1]), "=r"(d[2]), "=r"(d[3]) : "r"(addr));
}
__device__ __forceinline__ void mma16816(float* d, const uint32_t* a,
                                         uint32_t b0, uint32_t b1) {
    asm volatile(
        "mma.sync.aligned.m16n8k16.row.col.f32.bf16.bf16.f32 "
        "{%0,%1,%2,%3}, {%4,%5,%6,%7}, {%8,%9}, {%0,%1,%2,%3};"
        : "+f"(d[0]), "+f"(d[1]), "+f"(d[2]), "+f"(d[3])
        : "r"(a[0]), "r"(a[1]), "r"(a[2]), "r"(a[3]), "r"(b0), "r"(b1));
}
#define CP_ASYNC(dst, src) \
    asm volatile("cp.async.cg.shared.global [%0], [%1], 16;" :: "r"(dst), "l"(src))
#define CP_COMMIT() asm volatile("cp.async.commit_group;" ::: "memory")
#define CP_WAIT(n)  asm volatile("cp.async.wait_group %0;" :: "n"(n) : "memory")

// ---------------------------------------------------------------------------
// Conversion kernels
// ---------------------------------------------------------------------------
__global__ void conv_wvT_kernel(const float* __restrict__ Wv) {
    int idx = blockIdx.x * blockDim.x + threadIdx.x;
    if (idx >= D_ * D_) return;
    int n = idx / D_, d = idx % D_;
    int h = n >> 6, k = n & 63;
    split_store(g_wvTh, g_wvTl, idx, Wv[((size_t)h * D_ + d) * HS_ + k]);
}
__global__ void conv_wfT_kernel(const float* __restrict__ Wf) {
    int idx = blockIdx.x * blockDim.x + threadIdx.x;
    if (idx >= L_ * D_ * D_) return;
    int l = idx / (D_ * D_);
    int r = idx % (D_ * D_);
    int n = r / D_, d = r % D_;
    split_store(g_wfTh, g_wfTl, idx, Wf[(size_t)l * D_ * D_ + (size_t)d * D_ + n]);
}
__global__ void build_circ_kernel(const float* __restrict__ alpha) {
    int bid = blockIdx.x;           // h*1024 + i
    int h = bid >> 10, i = bid & 1023;
    const float* a = alpha + (size_t)h * N_;
    size_t base = (size_t)bid * N_;
    #pragma unroll
    for (int t = 0; t < 4; t++) {
        int j = threadIdx.x + t * 256;
        split_store(g_cch, g_ccl, base + j, a[(i - j) & (N_ - 1)]);
    }
}

// ---------------------------------------------------------------------------
// LayerNorm kernels
// ---------------------------------------------------------------------------
__device__ __forceinline__ void row_stats(const float* p, int t, float& mu, float& inv) {
    float v0 = p[t], v1 = p[t + 256], v2 = p[t + 512];
    float s = v0 + v1 + v2, q = v0*v0 + v1*v1 + v2*v2;
    #pragma unroll
    for (int o = 16; o; o >>= 1) {
        s += __shfl_xor_sync(0xffffffffu, s, o);
        q += __shfl_xor_sync(0xffffffffu, q, o);
    }
    __shared__ float red[16];
    int warp = t >> 5, lane = t & 31;
    if (lane == 0) { red[warp] = s; red[warp + 8] = q; }
    __syncthreads();
    if (t == 0) {
        float a = 0.f, b = 0.f;
        #pragma unroll
        for (int i = 0; i < 8; i++) { a += red[i]; b += red[i + 8]; }
        red[0] = a; red[8] = b;
    }
    __syncthreads();
    mu = red[0] * (1.f / D_);
    float var = red[8] * (1.f / D_) - mu * mu;
    inv = rsqrtf(var + EPS_);
}

__global__ void __launch_bounds__(256) ln1_kernel(
    const float* __restrict__ in, const float* __restrict__ scale,
    const float* __restrict__ bias)
{
    size_t row = blockIdx.x;
    const float* p = in + row * D_;
    int t = threadIdx.x;
    float mu, inv;
    row_stats(p, t, mu, inv);
    #pragma unroll
    for (int c = 0; c < 3; c++) {
        int col = t + c * 256;
        float val = (p[col] - mu) * inv * scale[col] + bias[col];
        split_store(g_xnh, g_xnl, row * D_ + col, val);
    }
}

__global__ void __launch_bounds__(256) ln_swish_kernel(
    const float* __restrict__ scale, const float* __restrict__ bias)
{
    size_t row = blockIdx.x;
    const float* p = g_t + row * D_;
    int t = threadIdx.x;
    float mu, inv;
    row_stats(p, t, mu, inv);
    #pragma unroll
    for (int c = 0; c < 3; c++) {
        int col = t + c * 256;
        float val = (p[col] - mu) * inv * scale[col] + bias[col];
        val = val * (1.f / (1.f + expf(-val)));
        g_z[row * D_ + col] = val;
        split_store(g_zh, g_zl, row * D_ + col, val);
    }
}

__global__ void final_kernel(float* __restrict__ out) {
    int i = blockIdx.x * blockDim.x + threadIdx.x;
    if (i >= M_ * D_) return;
    float s = g_z[i] + g_x1[i];
    float ax = fabsf(s);
    out[i] = ax + log1pf(expf(-2.f * ax)) - 0.69314718055994530942f;
}

// ---------------------------------------------------------------------------
// HMMA bf16-split GEMM. Block tile 128x128, BK=32, 3-stage cp.async pipeline.
//   D = Ah.Bh^T + Ah.Bl^T + Al.Bh^T   (A [M,K] rm, B [N,K] rm)
// 8 warps (2 m x 4 n), warp tile 64x32, m16n8k16 fragments.
// MODE 0: GEMM1   -> transpose via smem, scatter split(v) into [h][b*64+k][j]
// MODE 1: circul. -> x1 = x + D (fp32 + split), blockIdx.z = h
// MODE 2: FFN     -> t = D + bias (fp32)
// ---------------------------------------------------------------------------
#define TILE_B   8192u            // one 128x32 bf16 tile
#define STAGE_B  (4u*TILE_B)      // Ah, Al, Bh, Bl
#define NSTAGE   3
#define SMEM_BYTES (NSTAGE*STAGE_B)   // 98304 >= 66048 epi buffer

// smem chunk swizzle: row has 4 16B-chunks; chunk' = cc ^ ((row>>1)&3)
__device__ __forceinline__ uint32_t sw_off(int row, int cc) {
    return (uint32_t)(row * 64 + ((cc ^ ((row >> 1) & 3)) << 4));
}

__device__ __forceinline__ void cp_tile(uint32_t dstBase, const __nv_bfloat16* src,
                                        int rowBase, int kBase, int ld, int tid)
{
    const char* g = (const char*)src + ((size_t)rowBase * ld + kBase) * 2;
    #pragma unroll
    for (int t = 0; t < 2; t++) {
        int ci = tid + t * 256;
        int row = ci >> 2, cc = ci & 3;
        CP_ASYNC(dstBase + sw_off(row, cc), g + (size_t)row * ld * 2 + cc * 16);
    }
}

template<int MODE>
__global__ void __launch_bounds__(256, 1) tc_gemm(
    const __nv_bfloat16* __restrict__ Ah, const __nv_bfloat16* __restrict__ Al,
    const __nv_bfloat16* __restrict__ Bh, const __nv_bfloat16* __restrict__ Bl,
    int Kdim, size_t aStrZ, size_t bStrZ,
    const float* __restrict__ xin,            // mode1
    float* __restrict__ out_f,                // mode1: x1, mode2: t
    __nv_bfloat16* __restrict__ out_h,        // mode0: vch, mode1: x1h
    __nv_bfloat16* __restrict__ out_l,
    const float* __restrict__ bias)           // mode2
{
    extern __shared__ char smem[];
    const int tid = threadIdx.x;
    const int wid = tid >> 5, lane = tid & 31;
    const uint32_t sbase = smem_u32(smem);

    const int mBase = blockIdx.y * 128;
    const int nBase = blockIdx.x * 128;
    const int bz = blockIdx.z;
    const __nv_bfloat16* Abh = Ah + (size_t)bz * aStrZ;
    const __nv_bfloat16* Abl = Al + (size_t)bz * aStrZ;
    const __nv_bfloat16* Bbh = Bh + (size_t)bz * bStrZ;
    const __nv_bfloat16* Bbl = Bl + (size_t)bz * bStrZ;

    const int warpM = wid >> 2;     // 0..1
    const int warpN = wid & 3;      // 0..3

    const int nc = Kdim >> 5;       // BK = 32

    // prologue: stages 0,1
    #pragma unroll
    for (int s = 0; s < NSTAGE - 1; s++) {
        uint32_t sb = sbase + s * STAGE_B;
        cp_tile(sb,            Abh, mBase, s * 32, Kdim, tid);
        cp_tile(sb + TILE_B,   Abl, mBase, s * 32, Kdim, tid);
        cp_tile(sb + 2*TILE_B, Bbh, nBase, s * 32, Kdim, tid);
        cp_tile(sb + 3*TILE_B, Bbl, nBase, s * 32, Kdim, tid);
        CP_COMMIT();
    }

    float acc[4][4][4] = {};
    const int lrow = lane & 15;     // ldmatrix source row within 16
    const int lsel = lane >> 4;     // k-chunk select

    for (int c = 0; c < nc; c++) {
        CP_WAIT(NSTAGE - 2);
        __syncthreads();

        int pre = c + NSTAGE - 1;
        if (pre < nc) {
            uint32_t sb = sbase + (pre % NSTAGE) * STAGE_B;
            cp_tile(sb,            Abh, mBase, pre * 32, Kdim, tid);
            cp_tile(sb + TILE_B,   Abl, mBase, pre * 32, Kdim, tid);
            cp_tile(sb + 2*TILE_B, Bbh, nBase, pre * 32, Kdim, tid);
            cp_tile(sb + 3*TILE_B, Bbl, nBase, pre * 32, Kdim, tid);
            CP_COMMIT();
        }

        uint32_t stA = sbase + (c % NSTAGE) * STAGE_B;
        uint32_t stB = stA + 2*TILE_B;

        #pragma unroll
        for (int kk = 0; kk < 2; kk++) {
            int cc = kk * 2 + lsel;
            uint32_t aH[4][4], aL[4][4], bH[2][4], bL[2][4];
            #pragma unroll
            for (int mt = 0; mt < 4; mt++) {
                int r = warpM * 64 + mt * 16 + lrow;
                uint32_t o = sw_off(r, cc);
                ldsm_x4(aH[mt], stA + o);
                ldsm_x4(aL[mt], stA + TILE_B + o);
            }
            #pragma unroll
            for (int nt2 = 0; nt2 < 2; nt2++) {
                int r = warpN * 32 + nt2 * 16 + lrow;
                uint32_t o = sw_off(r, cc);
                ldsm_x4(bH[nt2], stB + o);
                ldsm_x4(bL[nt2], stB + TILE_B + o);
            }
            #pragma unroll
            for (int mt = 0; mt < 4; mt++)
                #pragma unroll
                for (int nt = 0; nt < 4; nt++) {
                    uint32_t h0 = bH[nt >> 1][nt & 1], h1 = bH[nt >> 1][(nt & 1) + 2];
                    uint32_t l0 = bL[nt >> 1][nt & 1], l1 = bL[nt >> 1][(nt & 1) + 2];
                    mma16816(acc[mt][nt], aH[mt], h0, h1);
                    mma16816(acc[mt][nt], aH[mt], l0, l1);
                    mma16816(acc[mt][nt], aL[mt], h0, h1);
                }
        }
    }
    CP_WAIT(0);
    __syncthreads();

    const int mBaseW = mBase + warpM * 64;
    const int nBaseW = nBase + warpN * 32;

    if (MODE == 0) {
        // stage C tile into smem [128][129] then write columns (contiguous in v)
        float* sbuf = reinterpret_cast<float*>(smem);
        const int LDS = 129;
        #pragma unroll
        for (int mt = 0; mt < 4; mt++)
            #pragma unroll
            for (int nt = 0; nt < 4; nt++) {
                int rl = warpM * 64 + mt * 16 + (lane >> 2);
                int cl = warpN * 32 + nt * 8 + ((lane & 3) << 1);
                sbuf[rl * LDS + cl]       = acc[mt][nt][0];
                sbuf[rl * LDS + cl + 1]   = acc[mt][nt][1];
                sbuf[(rl + 8) * LDS + cl]     = acc[mt][nt][2];
                sbuf[(rl + 8) * LDS + cl + 1] = acc[mt][nt][3];
            }
        __syncthreads();
        #pragma unroll
        for (int i = 0; i < 16; i++) {
            int cl = wid * 16 + i;
            int cg = nBase + cl;
            int h = cg >> 6, k = cg & 63;
            #pragma unroll
            for (int q = 0; q < 4; q++) {
                int m = q * 32 + lane;
                int mg = mBase + m;
                int b = mg >> 10, j = mg & 1023;
                size_t o = (((size_t)(h << 10) + (b << 6) + k) << 10) + j;
                split_store(out_h, out_l, o, sbuf[m * LDS + cl]);
            }
        }
    } else {
        #pragma unroll
        for (int mt = 0; mt < 4; mt++)
            #pragma unroll
            for (int nt = 0; nt < 4; nt++) {
                int i0 = mBaseW + mt * 16 + (lane >> 2);
                int cl = nBaseW + nt * 8 + ((lane & 3) << 1);
                #pragma unroll
                for (int half = 0; half < 2; half++) {
                    int i = i0 + half * 8;
                    float v0 = acc[mt][nt][half * 2];
                    float v1 = acc[mt][nt][half * 2 + 1];
                    if (MODE == 1) {
                        int b = cl >> 6, k = cl & 63;
                        size_t o = ((size_t)(b << 10) + i) * D_ + bz * HS_ + k;
                        float r0 = xin[o] + v0;
                        float r1 = xin[o + 1] + v1;
                        out_f[o] = r0; out_f[o + 1] = r1;
                        split_store(out_h, out_l, o, r0);
                        split_store(out_h, out_l, o + 1, r1);
                    } else {
                        size_t o = (size_t)i * D_ + cl;
                        out_f[o]     = v0 + bias[cl];
                        out_f[o + 1] = v1 + bias[cl + 1];
                    }
                }
            }
    }
}

// ---------------------------------------------------------------------------
// Launch
// ---------------------------------------------------------------------------
extern "C" void kernel_launch(void* const* d_in, const int* in_sizes, int n_in,
                              void* d_out, int out_size)
{
    const float* x     = (const float*)d_in[0];
    const float* ln1_s = (const float*)d_in[1];
    const float* ln1_b = (const float*)d_in[2];
    const float* Wv    = (const float*)d_in[3];
    const float* alpha = (const float*)d_in[4];
    const float* Wf    = (const float*)d_in[5];
    const float* bf    = (const float*)d_in[6];
    const float* lnf_s = (const float*)d_in[7];
    const float* lnf_b = (const float*)d_in[8];
    float* out = (float*)d_out;

    cudaFuncSetAttribute(tc_gemm<0>, cudaFuncAttributeMaxDynamicSharedMemorySize, SMEM_BYTES);
    cudaFuncSetAttribute(tc_gemm<1>, cudaFuncAttributeMaxDynamicSharedMemorySize, SMEM_BYTES);
    cudaFuncSetAttribute(tc_gemm<2>, cudaFuncAttributeMaxDynamicSharedMemorySize, SMEM_BYTES);

    __nv_bfloat16 *xnh, *xnl, *wvTh, *wvTl, *wfTh, *wfTl, *vch, *vcl, *cch, *ccl;
    __nv_bfloat16 *x1h, *x1l, *zh, *zl;
    float *x1, *t, *z;
    cudaGetSymbolAddress((void**)&xnh, g_xnh);   cudaGetSymbolAddress((void**)&xnl, g_xnl);
    cudaGetSymbolAddress((void**)&wvTh, g_wvTh); cudaGetSymbolAddress((void**)&wvTl, g_wvTl);
    cudaGetSymbolAddress((void**)&wfTh, g_wfTh); cudaGetSymbolAddress((void**)&wfTl, g_wfTl);
    cudaGetSymbolAddress((void**)&vch, g_vch);   cudaGetSymbolAddress((void**)&vcl, g_vcl);
    cudaGetSymbolAddress((void**)&cch, g_cch);   cudaGetSymbolAddress((void**)&ccl, g_ccl);
    cudaGetSymbolAddress((void**)&x1h, g_x1h);   cudaGetSymbolAddress((void**)&x1l, g_x1l);
    cudaGetSymbolAddress((void**)&zh, g_zh);     cudaGetSymbolAddress((void**)&zl, g_zl);
    cudaGetSymbolAddress((void**)&x1, g_x1);
    cudaGetSymbolAddress((void**)&t, g_t);
    cudaGetSymbolAddress((void**)&z, g_z);

    // operand prep
    conv_wvT_kernel<<<(D_*D_ + 255)/256, 256>>>(Wv);
    conv_wfT_kernel<<<(L_*D_*D_ + 255)/256, 256>>>(Wf);
    build_circ_kernel<<<H_*N_, 256>>>(alpha);
    ln1_kernel<<<M_, 256>>>(x, ln1_s, ln1_b);

    // GEMM1: v = xn @ Wv (scatter into circulant B layout)
    tc_gemm<0><<<dim3(D_/128, M_/128, 1), 256, SMEM_BYTES>>>(
        xnh, xnl, wvTh, wvTl, D_, 0, 0, nullptr, nullptr, vch, vcl, nullptr);

    // circulant: x1 = x + C @ v (per head)
    tc_gemm<1><<<dim3(N_/128, N_/128, H_), 256, SMEM_BYTES>>>(
        cch, ccl, vch, vcl, N_, (size_t)N_*N_, (size_t)N_*N_,
        x, x1, x1h, x1l, nullptr);

    // FFN x2
    tc_gemm<2><<<dim3(D_/128, M_/128, 1), 256, SMEM_BYTES>>>(
        x1h, x1l, wfTh, wfTl, D_, 0, 0, nullptr, t, nullptr, nullptr, bf);
    ln_swish_kernel<<<M_, 256>>>(lnf_s, lnf_b);

    tc_gemm<2><<<dim3(D_/128, M_/128, 1), 256, SMEM_BYTES>>>(
        zh, zl, wfTh + (size_t)D_*D_, wfTl + (size_t)D_*D_, D_, 0, 0,
        nullptr, t, nullptr, nullptr, bf + D_);
    ln_swish_kernel<<<M_, 256>>>(lnf_s + D_, lnf_b + D_);

    final_kernel<<<(M_*D_ + 255)/256, 256>>>(out);
}

// round 4
// speedup vs baseline: 3.8203x; 2.0765x over previous
#include <cuda_runtime.h>
#include <cuda_fp16.h>
#include <cstdint>

// ---------------------------------------------------------------------------
// Problem shape
// ---------------------------------------------------------------------------
#define B_  16
#define N_  1024
#define D_  768
#define H_  12
#define HS_ 64
#define M_  (B_*N_)     // 16384 token rows
#define L_  2
#define EPS_ 1e-6f

// ---------------------------------------------------------------------------
// Scratch (fp16 operands, fp32 residual path)
// ---------------------------------------------------------------------------
__device__ __half g_xn [M_*D_];        // LN1(x)           (GEMM1 A)
__device__ __half g_wvT[D_*D_];        // Wv^T [n=h*64+k][d]  (GEMM1 B)
__device__ __half g_wfT[L_*D_*D_];     // Wf^T [l][n][d]   (FFN B)
__device__ __half g_vc [H_*N_*N_];     // v [h][b*64+k][j] (circ B)
__device__ __half g_cc [H_*N_*N_];     // C [h][i][j]      (circ A)
__device__ float  g_x1 [M_*D_];        // residual x + y (fp32)
__device__ __half g_x1h[M_*D_];        // fp16 copy        (FFN1 A)
__device__ float  g_t  [M_*D_];        // ffn gemm out (fp32)
__device__ __half g_zh [M_*D_];        // swish(ln(t))     (FFN2 A)

// ---------------------------------------------------------------------------
// Helpers
// ---------------------------------------------------------------------------
__device__ __forceinline__ uint32_t smem_u32(const void* p) {
    uint32_t a;
    asm("{ .reg .u64 t; cvta.to.shared.u64 t, %1; cvt.u32.u64 %0, t; }"
        : "=r"(a) : "l"(p));
    return a;
}
__device__ __forceinline__ void ldsm_x4(uint32_t* d, uint32_t addr) {
    asm volatile("ldmatrix.sync.aligned.m8n8.x4.shared.b16 {%0,%1,%2,%3}, [%4];"
                 : "=r"(d[0]), "=r"(d[1]), "=r"(d[2]), "=r"(d[3]) : "r"(addr));
}
__device__ __forceinline__ void mma16816(float* d, const uint32_t* a,
                                         uint32_t b0, uint32_t b1) {
    asm volatile(
        "mma.sync.aligned.m16n8k16.row.col.f32.f16.f16.f32 "
        "{%0,%1,%2,%3}, {%4,%5,%6,%7}, {%8,%9}, {%0,%1,%2,%3};"
        : "+f"(d[0]), "+f"(d[1]), "+f"(d[2]), "+f"(d[3])
        : "r"(a[0]), "r"(a[1]), "r"(a[2]), "r"(a[3]), "r"(b0), "r"(b1));
}
#define CP_ASYNC(dst, src) \
    asm volatile("cp.async.cg.shared.global [%0], [%1], 16;" :: "r"(dst), "l"(src))
#define CP_COMMIT() asm volatile("cp.async.commit_group;" ::: "memory")
#define CP_WAIT(n)  asm volatile("cp.async.wait_group %0;" :: "n"(n) : "memory")

// ---------------------------------------------------------------------------
// Conversion kernels
// ---------------------------------------------------------------------------
__global__ void conv_wvT_kernel(const float* __restrict__ Wv) {
    int idx = blockIdx.x * blockDim.x + threadIdx.x;
    if (idx >= D_ * D_) return;
    int n = idx / D_, d = idx % D_;
    int h = n >> 6, k = n & 63;
    g_wvT[idx] = __float2half(Wv[((size_t)h * D_ + d) * HS_ + k]);
}
__global__ void conv_wfT_kernel(const float* __restrict__ Wf) {
    int idx = blockIdx.x * blockDim.x + threadIdx.x;
    if (idx >= L_ * D_ * D_) return;
    int l = idx / (D_ * D_);
    int r = idx % (D_ * D_);
    int n = r / D_, d = r % D_;
    g_wfT[idx] = __float2half(Wf[(size_t)l * D_ * D_ + (size_t)d * D_ + n]);
}
__global__ void build_circ_kernel(const float* __restrict__ alpha) {
    int bid = blockIdx.x;           // h*1024 + i
    int h = bid >> 10, i = bid & 1023;
    const float* a = alpha + (size_t)h * N_;
    size_t base = (size_t)bid * N_;
    #pragma unroll
    for (int t = 0; t < 4; t++) {
        int j = threadIdx.x + t * 256;
        g_cc[base + j] = __float2half(a[(i - j) & (N_ - 1)]);
    }
}

// ---------------------------------------------------------------------------
// LayerNorm kernels
// ---------------------------------------------------------------------------
__device__ __forceinline__ void row_stats(const float* p, int t, float& mu, float& inv) {
    float v0 = p[t], v1 = p[t + 256], v2 = p[t + 512];
    float s = v0 + v1 + v2, q = v0*v0 + v1*v1 + v2*v2;
    #pragma unroll
    for (int o = 16; o; o >>= 1) {
        s += __shfl_xor_sync(0xffffffffu, s, o);
        q += __shfl_xor_sync(0xffffffffu, q, o);
    }
    __shared__ float red[16];
    int warp = t >> 5, lane = t & 31;
    if (lane == 0) { red[warp] = s; red[warp + 8] = q; }
    __syncthreads();
    if (t == 0) {
        float a = 0.f, b = 0.f;
        #pragma unroll
        for (int i = 0; i < 8; i++) { a += red[i]; b += red[i + 8]; }
        red[0] = a; red[8] = b;
    }
    __syncthreads();
    mu = red[0] * (1.f / D_);
    float var = red[8] * (1.f / D_) - mu * mu;
    inv = rsqrtf(var + EPS_);
}

__global__ void __launch_bounds__(256) ln1_kernel(
    const float* __restrict__ in, const float* __restrict__ scale,
    const float* __restrict__ bias)
{
    size_t row = blockIdx.x;
    const float* p = in + row * D_;
    int t = threadIdx.x;
    float mu, inv;
    row_stats(p, t, mu, inv);
    #pragma unroll
    for (int c = 0; c < 3; c++) {
        int col = t + c * 256;
        float val = (p[col] - mu) * inv * scale[col] + bias[col];
        g_xn[row * D_ + col] = __float2half(val);
    }
}

// LAST=0: z = swish(LN(t)) -> g_zh (fp16)
// LAST=1: out = log_cosh(swish(LN(t)) + x1)
template<int LAST>
__global__ void __launch_bounds__(256) ln_swish_kernel(
    const float* __restrict__ scale, const float* __restrict__ bias,
    float* __restrict__ out)
{
    size_t row = blockIdx.x;
    const float* p = g_t + row * D_;
    int t = threadIdx.x;
    float mu, inv;
    row_stats(p, t, mu, inv);
    #pragma unroll
    for (int c = 0; c < 3; c++) {
        int col = t + c * 256;
        float val = (p[col] - mu) * inv * scale[col] + bias[col];
        val = val * (1.f / (1.f + expf(-val)));
        if (LAST) {
            float s = val + g_x1[row * D_ + col];
            float ax = fabsf(s);
            out[row * D_ + col] = ax + log1pf(expf(-2.f * ax))
                                  - 0.69314718055994530942f;
        } else {
            g_zh[row * D_ + col] = __float2half(val);
        }
    }
}

// ---------------------------------------------------------------------------
// HMMA fp16 single-pass GEMM. Block 128x128, BK=32, 4-stage cp.async.
//   D = A.B^T   (A [M,K] fp16 rm, B [N,K] fp16 rm, fp32 accumulate)
// 8 warps (2m x 4n), warp tile 64x32, m16n8k16.
// MODE 0: GEMM1   -> smem transpose, scatter v into [h][b*64+k][j] (fp16)
// MODE 1: circul. -> x1 = x + D (fp32 + fp16), blockIdx.z = h
// MODE 2: FFN     -> t = D + bias (fp32)
// ---------------------------------------------------------------------------
#define TILE_B   8192u            // one 128x32 fp16 tile
#define STAGE_B  (2u*TILE_B)      // A, B
#define NSTAGE   4
#define SMEM_BYTES 69632u         // max(4*16KB pipeline, 66KB epi buffer)

// smem chunk swizzle: row has 4 16B-chunks; chunk' = cc ^ ((row>>1)&3)
__device__ __forceinline__ uint32_t sw_off(int row, int cc) {
    return (uint32_t)(row * 64 + ((cc ^ ((row >> 1) & 3)) << 4));
}

__device__ __forceinline__ void cp_tile(uint32_t dstBase, const __half* src,
                                        int rowBase, int kBase, int ld, int tid)
{
    const char* g = (const char*)src + ((size_t)rowBase * ld + kBase) * 2;
    #pragma unroll
    for (int t = 0; t < 2; t++) {
        int ci = tid + t * 256;
        int row = ci >> 2, cc = ci & 3;
        CP_ASYNC(dstBase + sw_off(row, cc), g + (size_t)row * ld * 2 + cc * 16);
    }
}

template<int MODE>
__global__ void __launch_bounds__(256, 1) tc_gemm(
    const __half* __restrict__ A, const __half* __restrict__ Bm,
    int Kdim, size_t aStrZ, size_t bStrZ,
    const float* __restrict__ xin,            // mode1
    float* __restrict__ out_f,                // mode1: x1, mode2: t
    __half* __restrict__ out_h,               // mode0: vc, mode1: x1h
    const float* __restrict__ bias)           // mode2
{
    extern __shared__ char smem[];
    const int tid = threadIdx.x;
    const int wid = tid >> 5, lane = tid & 31;
    const uint32_t sbase = smem_u32(smem);

    const int mBase = blockIdx.y * 128;
    const int nBase = blockIdx.x * 128;
    const int bz = blockIdx.z;
    const __half* Ab = A  + (size_t)bz * aStrZ;
    const __half* Bb = Bm + (size_t)bz * bStrZ;

    const int warpM = wid >> 2;     // 0..1
    const int warpN = wid & 3;      // 0..3

    const int nc = Kdim >> 5;       // BK = 32

    #pragma unroll
    for (int s = 0; s < NSTAGE - 1; s++) {
        uint32_t sb = sbase + s * STAGE_B;
        cp_tile(sb,          Ab, mBase, s * 32, Kdim, tid);
        cp_tile(sb + TILE_B, Bb, nBase, s * 32, Kdim, tid);
        CP_COMMIT();
    }

    float acc[4][4][4] = {};
    const int lrow = lane & 15;     // ldmatrix source row within 16
    const int lsel = lane >> 4;     // k-chunk select

    for (int c = 0; c < nc; c++) {
        CP_WAIT(NSTAGE - 2);
        __syncthreads();

        int pre = c + NSTAGE - 1;
        if (pre < nc) {
            uint32_t sb = sbase + (pre % NSTAGE) * STAGE_B;
            cp_tile(sb,          Ab, mBase, pre * 32, Kdim, tid);
            cp_tile(sb + TILE_B, Bb, nBase, pre * 32, Kdim, tid);
            CP_COMMIT();
        }

        uint32_t stA = sbase + (c % NSTAGE) * STAGE_B;
        uint32_t stB = stA + TILE_B;

        #pragma unroll
        for (int kk = 0; kk < 2; kk++) {
            int cc = kk * 2 + lsel;
            uint32_t aF[4][4], bF[2][4];
            #pragma unroll
            for (int mt = 0; mt < 4; mt++) {
                int r = warpM * 64 + mt * 16 + lrow;
                ldsm_x4(aF[mt], stA + sw_off(r, cc));
            }
            #pragma unroll
            for (int nt2 = 0; nt2 < 2; nt2++) {
                int r = warpN * 32 + nt2 * 16 + lrow;
                ldsm_x4(bF[nt2], stB + sw_off(r, cc));
            }
            #pragma unroll
            for (int mt = 0; mt < 4; mt++)
                #pragma unroll
                for (int nt = 0; nt < 4; nt++) {
                    uint32_t b0 = bF[nt >> 1][nt & 1];
                    uint32_t b1 = bF[nt >> 1][(nt & 1) + 2];
                    mma16816(acc[mt][nt], aF[mt], b0, b1);
                }
        }
        __syncthreads();
    }
    CP_WAIT(0);

    const int mBaseW = mBase + warpM * 64;
    const int nBaseW = nBase + warpN * 32;

    if (MODE == 0) {
        // stage C tile into smem [128][129] then write columns (contiguous in v)
        float* sbuf = reinterpret_cast<float*>(smem);
        const int LDS = 129;
        __syncthreads();
        #pragma unroll
        for (int mt = 0; mt < 4; mt++)
            #pragma unroll
            for (int nt = 0; nt < 4; nt++) {
                int rl = warpM * 64 + mt * 16 + (lane >> 2);
                int cl = warpN * 32 + nt * 8 + ((lane & 3) << 1);
                sbuf[rl * LDS + cl]           = acc[mt][nt][0];
                sbuf[rl * LDS + cl + 1]       = acc[mt][nt][1];
                sbuf[(rl + 8) * LDS + cl]     = acc[mt][nt][2];
                sbuf[(rl + 8) * LDS + cl + 1] = acc[mt][nt][3];
            }
        __syncthreads();
        #pragma unroll
        for (int i = 0; i < 16; i++) {
            int cl = wid * 16 + i;
            int cg = nBase + cl;
            int h = cg >> 6, k = cg & 63;
            #pragma unroll
            for (int q = 0; q < 4; q++) {
                int m = q * 32 + lane;
                int mg = mBase + m;
                int b = mg >> 10, j = mg & 1023;
                size_t o = (((size_t)(h << 10) + (b << 6) + k) << 10) + j;
                out_h[o] = __float2half(sbuf[m * LDS + cl]);
            }
        }
    } else {
        #pragma unroll
        for (int mt = 0; mt < 4; mt++)
            #pragma unroll
            for (int nt = 0; nt < 4; nt++) {
                int i0 = mBaseW + mt * 16 + (lane >> 2);
                int cl = nBaseW + nt * 8 + ((lane & 3) << 1);
                #pragma unroll
                for (int half2 = 0; half2 < 2; half2++) {
                    int i = i0 + half2 * 8;
                    float v0 = acc[mt][nt][half2 * 2];
                    float v1 = acc[mt][nt][half2 * 2 + 1];
                    if (MODE == 1) {
                        int b = cl >> 6, k = cl & 63;
                        size_t o = ((size_t)(b << 10) + i) * D_ + bz * HS_ + k;
                        float r0 = xin[o] + v0;
                        float r1 = xin[o + 1] + v1;
                        out_f[o] = r0; out_f[o + 1] = r1;
                        out_h[o] = __float2half(r0);
                        out_h[o + 1] = __float2half(r1);
                    } else {
                        size_t o = (size_t)i * D_ + cl;
                        out_f[o]     = v0 + bias[cl];
                        out_f[o + 1] = v1 + bias[cl + 1];
                    }
                }
            }
    }
}

// ---------------------------------------------------------------------------
// Launch
// ---------------------------------------------------------------------------
extern "C" void kernel_launch(void* const* d_in, const int* in_sizes, int n_in,
                              void* d_out, int out_size)
{
    const float* x     = (const float*)d_in[0];
    const float* ln1_s = (const float*)d_in[1];
    const float* ln1_b = (const float*)d_in[2];
    const float* Wv    = (const float*)d_in[3];
    const float* alpha = (const float*)d_in[4];
    const float* Wf    = (const float*)d_in[5];
    const float* bf    = (const float*)d_in[6];
    const float* lnf_s = (const float*)d_in[7];
    const float* lnf_b = (const float*)d_in[8];
    float* out = (float*)d_out;

    cudaFuncSetAttribute(tc_gemm<0>, cudaFuncAttributeMaxDynamicSharedMemorySize, SMEM_BYTES);
    cudaFuncSetAttribute(tc_gemm<1>, cudaFuncAttributeMaxDynamicSharedMemorySize, SMEM_BYTES);
    cudaFuncSetAttribute(tc_gemm<2>, cudaFuncAttributeMaxDynamicSharedMemorySize, SMEM_BYTES);

    __half *xn, *wvT, *wfT, *vc, *cc, *x1h, *zh;
    float *x1, *t;
    cudaGetSymbolAddress((void**)&xn, g_xn);
    cudaGetSymbolAddress((void**)&wvT, g_wvT);
    cudaGetSymbolAddress((void**)&wfT, g_wfT);
    cudaGetSymbolAddress((void**)&vc, g_vc);
    cudaGetSymbolAddress((void**)&cc, g_cc);
    cudaGetSymbolAddress((void**)&x1h, g_x1h);
    cudaGetSymbolAddress((void**)&zh, g_zh);
    cudaGetSymbolAddress((void**)&x1, g_x1);
    cudaGetSymbolAddress((void**)&t, g_t);

    // operand prep
    conv_wvT_kernel<<<(D_*D_ + 255)/256, 256>>>(Wv);
    conv_wfT_kernel<<<(L_*D_*D_ + 255)/256, 256>>>(Wf);
    build_circ_kernel<<<H_*N_, 256>>>(alpha);
    ln1_kernel<<<M_, 256>>>(x, ln1_s, ln1_b);

    // GEMM1: v = xn @ Wv (scatter into circulant B layout)
    tc_gemm<0><<<dim3(D_/128, M_/128, 1), 256, SMEM_BYTES>>>(
        xn, wvT, D_, 0, 0, nullptr, nullptr, vc, nullptr);

    // circulant: x1 = x + C @ v (per head)
    tc_gemm<1><<<dim3(N_/128, N_/128, H_), 256, SMEM_BYTES>>>(
        cc, vc, N_, (size_t)N_*N_, (size_t)N_*N_, x, x1, x1h, nullptr);

    // FFN1
    tc_gemm<2><<<dim3(D_/128, M_/128, 1), 256, SMEM_BYTES>>>(
        x1h, wfT, D_, 0, 0, nullptr, t, nullptr, bf);
    ln_swish_kernel<0><<<M_, 256>>>(lnf_s, lnf_b, nullptr);

    // FFN2
    tc_gemm<2><<<dim3(D_/128, M_/128, 1), 256, SMEM_BYTES>>>(
        zh, wfT + (size_t)D_*D_, D_, 0, 0, nullptr, t, nullptr, bf + D_);
    ln_swish_kernel<1><<<M_, 256>>>(lnf_s + D_, lnf_b + D_, out);
}

// round 5
// speedup vs baseline: 4.4552x; 1.1662x over previous
#include <cuda_runtime.h>
#include <cuda_fp16.h>
#include <cstdint>

// ---------------------------------------------------------------------------
// Problem shape
// ---------------------------------------------------------------------------
#define B_  16
#define N_  1024
#define D_  768
#define H_  12
#define HS_ 64
#define M_  (B_*N_)     // 16384 token rows
#define L_  2
#define EPS_ 1e-6f

// ---------------------------------------------------------------------------
// Scratch
// ---------------------------------------------------------------------------
__device__ __half g_xn [M_*D_];        // LN1(x)           (GEMM1 A)
__device__ __half g_wvT[D_*D_];        // Wv^T [n=h*64+k][d]
__device__ __half g_wfT[L_*D_*D_];     // Wf^T [l][n][d]
__device__ __half g_vc [H_*N_*N_];     // v [h][b*64+k][j] (circ B)
__device__ __half g_cc [H_*N_*N_];     // C [h][i][j]      (circ A)
__device__ float  g_x1 [M_*D_];        // residual x + y (fp32)
__device__ __half g_x1h[M_*D_];        // fp16 copy        (FFN1 A)
__device__ float  g_t  [M_*D_];        // ffn gemm out (fp32)
__device__ __half g_zh [M_*D_];        // swish(ln(t))     (FFN2 A)

// ---------------------------------------------------------------------------
// Helpers
// ---------------------------------------------------------------------------
__device__ __forceinline__ uint32_t smem_u32(const void* p) {
    uint32_t a;
    asm("{ .reg .u64 t; cvta.to.shared.u64 t, %1; cvt.u32.u64 %0, t; }"
        : "=r"(a) : "l"(p));
    return a;
}
__device__ __forceinline__ void ldsm_x4(uint32_t* d, uint32_t addr) {
    asm volatile("ldmatrix.sync.aligned.m8n8.x4.shared.b16 {%0,%1,%2,%3}, [%4];"
                 : "=r"(d[0]), "=r"(d[1]), "=r"(d[2]), "=r"(d[3]) : "r"(addr));
}
__device__ __forceinline__ void mma16816(float* d, const uint32_t* a,
                                         uint32_t b0, uint32_t b1) {
    asm volatile(
        "mma.sync.aligned.m16n8k16.row.col.f32.f16.f16.f32 "
        "{%0,%1,%2,%3}, {%4,%5,%6,%7}, {%8,%9}, {%0,%1,%2,%3};"
        : "+f"(d[0]), "+f"(d[1]), "+f"(d[2]), "+f"(d[3])
        : "r"(a[0]), "r"(a[1]), "r"(a[2]), "r"(a[3]), "r"(b0), "r"(b1));
}
#define CP_ASYNC(dst, src) \
    asm volatile("cp.async.cg.shared.global [%0], [%1], 16;" :: "r"(dst), "l"(src))
#define CP_COMMIT() asm volatile("cp.async.commit_group;" ::: "memory")
#define CP_WAIT(n)  asm volatile("cp.async.wait_group %0;" :: "n"(n) : "memory")

// ---------------------------------------------------------------------------
// Conversion kernels
// ---------------------------------------------------------------------------
__global__ void conv_wvT_kernel(const float* __restrict__ Wv) {
    int idx = blockIdx.x * blockDim.x + threadIdx.x;
    if (idx >= D_ * D_) return;
    int n = idx / D_, d = idx % D_;
    int h = n >> 6, k = n & 63;
    g_wvT[idx] = __float2half(Wv[((size_t)h * D_ + d) * HS_ + k]);
}
__global__ void conv_wfT_kernel(const float* __restrict__ Wf) {
    int idx = blockIdx.x * blockDim.x + threadIdx.x;
    if (idx >= L_ * D_ * D_) return;
    int l = idx / (D_ * D_);
    int r = idx % (D_ * D_);
    int n = r / D_, d = r % D_;
    g_wfT[idx] = __float2half(Wf[(size_t)l * D_ * D_ + (size_t)d * D_ + n]);
}
__global__ void build_circ_kernel(const float* __restrict__ alpha) {
    int bid = blockIdx.x;           // h*1024 + i
    int h = bid >> 10, i = bid & 1023;
    const float* a = alpha + (size_t)h * N_;
    size_t base = (size_t)bid * N_;
    #pragma unroll
    for (int t = 0; t < 4; t++) {
        int j = threadIdx.x + t * 256;
        g_cc[base + j] = __float2half(a[(i - j) & (N_ - 1)]);
    }
}

// ---------------------------------------------------------------------------
// Warp-per-row LayerNorm (no smem, shuffle reduction). 8 rows/block.
// ---------------------------------------------------------------------------
__device__ __forceinline__ void warp_stats(const float4* v, float& mu, float& inv) {
    float s = 0.f, q = 0.f;
    #pragma unroll
    for (int i = 0; i < 6; i++) {
        s += v[i].x + v[i].y + v[i].z + v[i].w;
        q += v[i].x*v[i].x + v[i].y*v[i].y + v[i].z*v[i].z + v[i].w*v[i].w;
    }
    #pragma unroll
    for (int o = 16; o; o >>= 1) {
        s += __shfl_xor_sync(0xffffffffu, s, o);
        q += __shfl_xor_sync(0xffffffffu, q, o);
    }
    mu = s * (1.f / D_);
    float var = q * (1.f / D_) - mu * mu;
    inv = rsqrtf(var + EPS_);
}

__global__ void __launch_bounds__(256) ln1_kernel(
    const float* __restrict__ in, const float* __restrict__ scale,
    const float* __restrict__ bias)
{
    int warp = threadIdx.x >> 5, lane = threadIdx.x & 31;
    size_t row = (size_t)blockIdx.x * 8 + warp;
    const float4* p = reinterpret_cast<const float4*>(in + row * D_);
    const float4* sc = reinterpret_cast<const float4*>(scale);
    const float4* bi = reinterpret_cast<const float4*>(bias);
    float4 v[6];
    #pragma unroll
    for (int i = 0; i < 6; i++) v[i] = p[lane + 32 * i];
    float mu, inv;
    warp_stats(v, mu, inv);
    #pragma unroll
    for (int i = 0; i < 6; i++) {
        int g4 = lane + 32 * i;
        float4 s4 = sc[g4], b4 = bi[g4];
        __half2 h0 = __floats2half2_rn((v[i].x - mu) * inv * s4.x + b4.x,
                                       (v[i].y - mu) * inv * s4.y + b4.y);
        __half2 h1 = __floats2half2_rn((v[i].z - mu) * inv * s4.z + b4.z,
                                       (v[i].w - mu) * inv * s4.w + b4.w);
        uint2 u; u.x = *(uint32_t*)&h0; u.y = *(uint32_t*)&h1;
        *reinterpret_cast<uint2*>(g_xn + row * D_ + g4 * 4) = u;
    }
}

// LAST=0: z = swish(LN(t)) -> g_zh ; LAST=1: out = log_cosh(swish(LN(t)) + x1)
template<int LAST>
__global__ void __launch_bounds__(256) ln_swish_kernel(
    const float* __restrict__ scale, const float* __restrict__ bias,
    float* __restrict__ out)
{
    int warp = threadIdx.x >> 5, lane = threadIdx.x & 31;
    size_t row = (size_t)blockIdx.x * 8 + warp;
    const float4* p = reinterpret_cast<const float4*>(g_t + row * D_);
    const float4* sc = reinterpret_cast<const float4*>(scale);
    const float4* bi = reinterpret_cast<const float4*>(bias);
    float4 v[6];
    #pragma unroll
    for (int i = 0; i < 6; i++) v[i] = p[lane + 32 * i];
    float mu, inv;
    warp_stats(v, mu, inv);
    #pragma unroll
    for (int i = 0; i < 6; i++) {
        int g4 = lane + 32 * i;
        float4 s4 = sc[g4], b4 = bi[g4];
        float r[4] = {(v[i].x - mu) * inv * s4.x + b4.x,
                      (v[i].y - mu) * inv * s4.y + b4.y,
                      (v[i].z - mu) * inv * s4.z + b4.z,
                      (v[i].w - mu) * inv * s4.w + b4.w};
        #pragma unroll
        for (int c = 0; c < 4; c++) r[c] = r[c] * (1.f / (1.f + expf(-r[c])));
        if (LAST) {
            float4 xr = *reinterpret_cast<const float4*>(g_x1 + row * D_ + g4 * 4);
            float xs[4] = {xr.x, xr.y, xr.z, xr.w};
            float4 o4;
            float* po = &o4.x;
            #pragma unroll
            for (int c = 0; c < 4; c++) {
                float sum = r[c] + xs[c];
                float ax = fabsf(sum);
                po[c] = ax + log1pf(expf(-2.f * ax)) - 0.69314718055994530942f;
            }
            *reinterpret_cast<float4*>(out + row * D_ + g4 * 4) = o4;
        } else {
            __half2 h0 = __floats2half2_rn(r[0], r[1]);
            __half2 h1 = __floats2half2_rn(r[2], r[3]);
            uint2 u; u.x = *(uint32_t*)&h0; u.y = *(uint32_t*)&h1;
            *reinterpret_cast<uint2*>(g_zh + row * D_ + g4 * 4) = u;
        }
    }
}

// ---------------------------------------------------------------------------
// HMMA fp16 GEMM. Block 128x128, BK=64, 3-stage cp.async, 1 sync/iter.
//   D = A.B^T   (A [M,K] fp16 rm, B [N,K] fp16 rm, fp32 accumulate)
// 8 warps (2m x 4n), warp tile 64x32, m16n8k16.
// MODE 0: GEMM1   -> smem transpose, scatter v into [h][b*64+k][j] (fp16)
// MODE 1: circul. -> x1 = x + D (fp32 + fp16), blockIdx.z = h
// MODE 2: FFN     -> t = D + bias (fp32)
// ---------------------------------------------------------------------------
#define TILE_B   16384u           // one 128x64 fp16 tile (128 rows x 128B)
#define STAGE_B  (2u*TILE_B)      // A, B
#define NSTAGE   3
#define SMEM_BYTES (NSTAGE*STAGE_B)  // 98304 >= 66048 epi buffer

// 128B-row swizzle: 8 chunks of 16B; chunk' = cc ^ (row & 7)
__device__ __forceinline__ uint32_t sw_off(int row, int cc) {
    return (uint32_t)(row * 128 + ((cc ^ (row & 7)) << 4));
}

__device__ __forceinline__ void cp_tile(uint32_t dstBase, const __half* src,
                                        int rowBase, int kBase, int ld, int tid)
{
    const char* g = (const char*)src + ((size_t)rowBase * ld + kBase) * 2;
    #pragma unroll
    for (int t = 0; t < 4; t++) {
        int ci = tid + t * 256;
        int row = ci >> 3, cc = ci & 7;
        CP_ASYNC(dstBase + sw_off(row, cc), g + (size_t)row * ld * 2 + cc * 16);
    }
}

template<int MODE>
__global__ void __launch_bounds__(256, 1) tc_gemm(
    const __half* __restrict__ A, const __half* __restrict__ Bm,
    int Kdim, size_t aStrZ, size_t bStrZ,
    const float* __restrict__ xin,            // mode1
    float* __restrict__ out_f,                // mode1: x1, mode2: t
    __half* __restrict__ out_h,               // mode0: vc, mode1: x1h
    const float* __restrict__ bias)           // mode2
{
    extern __shared__ char smem[];
    const int tid = threadIdx.x;
    const int wid = tid >> 5, lane = tid & 31;
    const uint32_t sbase = smem_u32(smem);

    const int mBase = blockIdx.y * 128;
    const int nBase = blockIdx.x * 128;
    const int bz = blockIdx.z;
    const __half* Ab = A  + (size_t)bz * aStrZ;
    const __half* Bb = Bm + (size_t)bz * bStrZ;

    const int warpM = wid >> 2;     // 0..1
    const int warpN = wid & 3;      // 0..3

    const int nc = Kdim >> 6;       // BK = 64

    #pragma unroll
    for (int s = 0; s < NSTAGE - 1; s++) {
        uint32_t sb = sbase + s * STAGE_B;
        cp_tile(sb,          Ab, mBase, s * 64, Kdim, tid);
        cp_tile(sb + TILE_B, Bb, nBase, s * 64, Kdim, tid);
        CP_COMMIT();
    }

    float acc[4][4][4] = {};
    const int lrow = lane & 15;     // ldmatrix source row within 16
    const int lsel = lane >> 4;     // 16B column select

    for (int c = 0; c < nc; c++) {
        CP_WAIT(NSTAGE - 2);
        __syncthreads();

        int pre = c + NSTAGE - 1;
        if (pre < nc) {
            uint32_t sb = sbase + (pre % NSTAGE) * STAGE_B;
            cp_tile(sb,          Ab, mBase, pre * 64, Kdim, tid);
            cp_tile(sb + TILE_B, Bb, nBase, pre * 64, Kdim, tid);
            CP_COMMIT();
        }

        uint32_t stA = sbase + (c % NSTAGE) * STAGE_B;
        uint32_t stB = stA + TILE_B;

        #pragma unroll
        for (int kk = 0; kk < 4; kk++) {
            int cc = kk * 2 + lsel;
            uint32_t aF[4][4], bF[2][4];
            #pragma unroll
            for (int mt = 0; mt < 4; mt++) {
                int r = warpM * 64 + mt * 16 + lrow;
                ldsm_x4(aF[mt], stA + sw_off(r, cc));
            }
            #pragma unroll
            for (int nt2 = 0; nt2 < 2; nt2++) {
                int r = warpN * 32 + nt2 * 16 + lrow;
                ldsm_x4(bF[nt2], stB + sw_off(r, cc));
            }
            #pragma unroll
            for (int mt = 0; mt < 4; mt++)
                #pragma unroll
                for (int nt = 0; nt < 4; nt++) {
                    uint32_t b0 = bF[nt >> 1][nt & 1];
                    uint32_t b1 = bF[nt >> 1][(nt & 1) + 2];
                    mma16816(acc[mt][nt], aF[mt], b0, b1);
                }
        }
    }
    CP_WAIT(0);

    const int mBaseW = mBase + warpM * 64;
    const int nBaseW = nBase + warpN * 32;

    if (MODE == 0) {
        // stage C tile into smem [128][129] then write columns (contiguous in j)
        float* sbuf = reinterpret_cast<float*>(smem);
        const int LDS = 129;
        __syncthreads();
        #pragma unroll
        for (int mt = 0; mt < 4; mt++)
            #pragma unroll
            for (int nt = 0; nt < 4; nt++) {
                int rl = warpM * 64 + mt * 16 + (lane >> 2);
                int cl = warpN * 32 + nt * 8 + ((lane & 3) << 1);
                sbuf[rl * LDS + cl]           = acc[mt][nt][0];
                sbuf[rl * LDS + cl + 1]       = acc[mt][nt][1];
                sbuf[(rl + 8) * LDS + cl]     = acc[mt][nt][2];
                sbuf[(rl + 8) * LDS + cl + 1] = acc[mt][nt][3];
            }
        __syncthreads();
        #pragma unroll
        for (int i = 0; i < 16; i++) {
            int cl = wid * 16 + i;
            int cg = nBase + cl;
            int h = cg >> 6, k = cg & 63;
            #pragma unroll
            for (int q = 0; q < 2; q++) {
                int m = q * 64 + lane * 2;
                int mg = mBase + m;
                int b = mg >> 10, j = mg & 1023;
                size_t o = (((size_t)(h << 10) + (b << 6) + k) << 10) + j;
                __half2 hv = __floats2half2_rn(sbuf[m * LDS + cl],
                                               sbuf[(m + 1) * LDS + cl]);
                *reinterpret_cast<__half2*>(out_h + o) = hv;
            }
        }
    } else {
        #pragma unroll
        for (int mt = 0; mt < 4; mt++)
            #pragma unroll
            for (int nt = 0; nt < 4; nt++) {
                int i0 = mBaseW + mt * 16 + (lane >> 2);
                int cl = nBaseW + nt * 8 + ((lane & 3) << 1);
                #pragma unroll
                for (int half2i = 0; half2i < 2; half2i++) {
                    int i = i0 + half2i * 8;
                    float v0 = acc[mt][nt][half2i * 2];
                    float v1 = acc[mt][nt][half2i * 2 + 1];
                    if (MODE == 1) {
                        int b = cl >> 6, k = cl & 63;
                        size_t o = ((size_t)(b << 10) + i) * D_ + bz * HS_ + k;
                        float r0 = xin[o] + v0;
                        float r1 = xin[o + 1] + v1;
                        out_f[o] = r0; out_f[o + 1] = r1;
                        *reinterpret_cast<__half2*>(out_h + o) =
                            __floats2half2_rn(r0, r1);
                    } else {
                        size_t o = (size_t)i * D_ + cl;
                        out_f[o]     = v0 + bias[cl];
                        out_f[o + 1] = v1 + bias[cl + 1];
                    }
                }
            }
    }
}

// ---------------------------------------------------------------------------
// Launch
// ---------------------------------------------------------------------------
extern "C" void kernel_launch(void* const* d_in, const int* in_sizes, int n_in,
                              void* d_out, int out_size)
{
    const float* x     = (const float*)d_in[0];
    const float* ln1_s = (const float*)d_in[1];
    const float* ln1_b = (const float*)d_in[2];
    const float* Wv    = (const float*)d_in[3];
    const float* alpha = (const float*)d_in[4];
    const float* Wf    = (const float*)d_in[5];
    const float* bf    = (const float*)d_in[6];
    const float* lnf_s = (const float*)d_in[7];
    const float* lnf_b = (const float*)d_in[8];
    float* out = (float*)d_out;

    cudaFuncSetAttribute(tc_gemm<0>, cudaFuncAttributeMaxDynamicSharedMemorySize, SMEM_BYTES);
    cudaFuncSetAttribute(tc_gemm<1>, cudaFuncAttributeMaxDynamicSharedMemorySize, SMEM_BYTES);
    cudaFuncSetAttribute(tc_gemm<2>, cudaFuncAttributeMaxDynamicSharedMemorySize, SMEM_BYTES);

    __half *xn, *wvT, *wfT, *vc, *cc, *x1h, *zh;
    float *x1, *t;
    cudaGetSymbolAddress((void**)&xn, g_xn);
    cudaGetSymbolAddress((void**)&wvT, g_wvT);
    cudaGetSymbolAddress((void**)&wfT, g_wfT);
    cudaGetSymbolAddress((void**)&vc, g_vc);
    cudaGetSymbolAddress((void**)&cc, g_cc);
    cudaGetSymbolAddress((void**)&x1h, g_x1h);
    cudaGetSymbolAddress((void**)&zh, g_zh);
    cudaGetSymbolAddress((void**)&x1, g_x1);
    cudaGetSymbolAddress((void**)&t, g_t);

    // operand prep
    conv_wvT_kernel<<<(D_*D_ + 255)/256, 256>>>(Wv);
    conv_wfT_kernel<<<(L_*D_*D_ + 255)/256, 256>>>(Wf);
    build_circ_kernel<<<H_*N_, 256>>>(alpha);
    ln1_kernel<<<M_/8, 256>>>(x, ln1_s, ln1_b);

    // GEMM1: v = xn @ Wv (scatter into circulant B layout)
    tc_gemm<0><<<dim3(D_/128, M_/128, 1), 256, SMEM_BYTES>>>(
        xn, wvT, D_, 0, 0, nullptr, nullptr, vc, nullptr);

    // circulant: x1 = x + C @ v (per head)
    tc_gemm<1><<<dim3(N_/128, N_/128, H_), 256, SMEM_BYTES>>>(
        cc, vc, N_, (size_t)N_*N_, (size_t)N_*N_, x, x1, x1h, nullptr);

    // FFN1
    tc_gemm<2><<<dim3(D_/128, M_/128, 1), 256, SMEM_BYTES>>>(
        x1h, wfT, D_, 0, 0, nullptr, t, nullptr, bf);
    ln_swish_kernel<0><<<M_/8, 256>>>(lnf_s, lnf_b, nullptr);

    // FFN2
    tc_gemm<2><<<dim3(D_/128, M_/128, 1), 256, SMEM_BYTES>>>(
        zh, wfT + (size_t)D_*D_, D_, 0, 0, nullptr, t, nullptr, bf + D_);
    ln_swish_kernel<1><<<M_/8, 256>>>(lnf_s + D_, lnf_b + D_, out);
}

// round 6
// speedup vs baseline: 4.5302x; 1.0168x over previous
#include <cuda_runtime.h>
#include <cuda_fp16.h>
#include <cstdint>

// ---------------------------------------------------------------------------
// Problem shape
// ---------------------------------------------------------------------------
#define B_  16
#define N_  1024
#define D_  768
#define H_  12
#define HS_ 64
#define M_  (B_*N_)     // 16384 token rows
#define L_  2
#define EPS_ 1e-6f

// ---------------------------------------------------------------------------
// Scratch
// ---------------------------------------------------------------------------
__device__ __half g_xn [M_*D_];        // LN1(x)           (GEMM1 A)
__device__ __half g_wvT[D_*D_];        // Wv^T [n=h*64+k][d]
__device__ __half g_wfT[L_*D_*D_];     // Wf^T [l][n][d]
__device__ __half g_vc [H_*N_*N_];     // v [h][b*64+k][j] (circ B)
__device__ __half g_cc [H_*N_*N_];     // C [h][i][j]      (circ A)
__device__ float  g_x1 [M_*D_];        // residual x + y (fp32)
__device__ __half g_x1h[M_*D_];        // fp16 copy        (FFN1 A)
__device__ float  g_t  [M_*D_];        // ffn gemm out (fp32)
__device__ __half g_zh [M_*D_];        // swish(ln(t))     (FFN2 A)

// ---------------------------------------------------------------------------
// Helpers
// ---------------------------------------------------------------------------
__device__ __forceinline__ uint32_t smem_u32(const void* p) {
    uint32_t a;
    asm("{ .reg .u64 t; cvta.to.shared.u64 t, %1; cvt.u32.u64 %0, t; }"
        : "=r"(a) : "l"(p));
    return a;
}
__device__ __forceinline__ void ldsm_x4(uint32_t* d, uint32_t addr) {
    asm volatile("ldmatrix.sync.aligned.m8n8.x4.shared.b16 {%0,%1,%2,%3}, [%4];"
                 : "=r"(d[0]), "=r"(d[1]), "=r"(d[2]), "=r"(d[3]) : "r"(addr));
}
__device__ __forceinline__ void mma16816(float* d, const uint32_t* a,
                                         uint32_t b0, uint32_t b1) {
    asm volatile(
        "mma.sync.aligned.m16n8k16.row.col.f32.f16.f16.f32 "
        "{%0,%1,%2,%3}, {%4,%5,%6,%7}, {%8,%9}, {%0,%1,%2,%3};"
        : "+f"(d[0]), "+f"(d[1]), "+f"(d[2]), "+f"(d[3])
        : "r"(a[0]), "r"(a[1]), "r"(a[2]), "r"(a[3]), "r"(b0), "r"(b1));
}
#define CP_ASYNC(dst, src) \
    asm volatile("cp.async.cg.shared.global [%0], [%1], 16;" :: "r"(dst), "l"(src))
#define CP_COMMIT() asm volatile("cp.async.commit_group;" ::: "memory")
#define CP_WAIT(n)  asm volatile("cp.async.wait_group %0;" :: "n"(n) : "memory")

// ---------------------------------------------------------------------------
// Conversion kernels
// ---------------------------------------------------------------------------
__global__ void conv_wvT_kernel(const float* __restrict__ Wv) {
    int idx = blockIdx.x * blockDim.x + threadIdx.x;
    if (idx >= D_ * D_) return;
    int n = idx / D_, d = idx % D_;
    int h = n >> 6, k = n & 63;
    g_wvT[idx] = __float2half(Wv[((size_t)h * D_ + d) * HS_ + k]);
}
__global__ void conv_wfT_kernel(const float* __restrict__ Wf) {
    int idx = blockIdx.x * blockDim.x + threadIdx.x;
    if (idx >= L_ * D_ * D_) return;
    int l = idx / (D_ * D_);
    int r = idx % (D_ * D_);
    int n = r / D_, d = r % D_;
    g_wfT[idx] = __float2half(Wf[(size_t)l * D_ * D_ + (size_t)d * D_ + n]);
}
__global__ void build_circ_kernel(const float* __restrict__ alpha) {
    int bid = blockIdx.x;           // h*1024 + i
    int h = bid >> 10, i = bid & 1023;
    const float* a = alpha + (size_t)h * N_;
    size_t base = (size_t)bid * N_;
    #pragma unroll
    for (int t = 0; t < 4; t++) {
        int j = threadIdx.x + t * 256;
        g_cc[base + j] = __float2half(a[(i - j) & (N_ - 1)]);
    }
}

// ---------------------------------------------------------------------------
// Warp-per-row LayerNorm (no smem, shuffle reduction). 8 rows/block.
// ---------------------------------------------------------------------------
__device__ __forceinline__ void warp_stats(const float4* v, float& mu, float& inv) {
    float s = 0.f, q = 0.f;
    #pragma unroll
    for (int i = 0; i < 6; i++) {
        s += v[i].x + v[i].y + v[i].z + v[i].w;
        q += v[i].x*v[i].x + v[i].y*v[i].y + v[i].z*v[i].z + v[i].w*v[i].w;
    }
    #pragma unroll
    for (int o = 16; o; o >>= 1) {
        s += __shfl_xor_sync(0xffffffffu, s, o);
        q += __shfl_xor_sync(0xffffffffu, q, o);
    }
    mu = s * (1.f / D_);
    float var = q * (1.f / D_) - mu * mu;
    inv = rsqrtf(var + EPS_);
}

__global__ void __launch_bounds__(256) ln1_kernel(
    const float* __restrict__ in, const float* __restrict__ scale,
    const float* __restrict__ bias)
{
    int warp = threadIdx.x >> 5, lane = threadIdx.x & 31;
    size_t row = (size_t)blockIdx.x * 8 + warp;
    const float4* p = reinterpret_cast<const float4*>(in + row * D_);
    const float4* sc = reinterpret_cast<const float4*>(scale);
    const float4* bi = reinterpret_cast<const float4*>(bias);
    float4 v[6];
    #pragma unroll
    for (int i = 0; i < 6; i++) v[i] = p[lane + 32 * i];
    float mu, inv;
    warp_stats(v, mu, inv);
    #pragma unroll
    for (int i = 0; i < 6; i++) {
        int g4 = lane + 32 * i;
        float4 s4 = sc[g4], b4 = bi[g4];
        __half2 h0 = __floats2half2_rn((v[i].x - mu) * inv * s4.x + b4.x,
                                       (v[i].y - mu) * inv * s4.y + b4.y);
        __half2 h1 = __floats2half2_rn((v[i].z - mu) * inv * s4.z + b4.z,
                                       (v[i].w - mu) * inv * s4.w + b4.w);
        uint2 u; u.x = *(uint32_t*)&h0; u.y = *(uint32_t*)&h1;
        *reinterpret_cast<uint2*>(g_xn + row * D_ + g4 * 4) = u;
    }
}

// LAST=0: z = swish(LN(t)) -> g_zh ; LAST=1: out = log_cosh(swish(LN(t)) + x1)
template<int LAST>
__global__ void __launch_bounds__(256) ln_swish_kernel(
    const float* __restrict__ scale, const float* __restrict__ bias,
    float* __restrict__ out)
{
    int warp = threadIdx.x >> 5, lane = threadIdx.x & 31;
    size_t row = (size_t)blockIdx.x * 8 + warp;
    const float4* p = reinterpret_cast<const float4*>(g_t + row * D_);
    const float4* sc = reinterpret_cast<const float4*>(scale);
    const float4* bi = reinterpret_cast<const float4*>(bias);
    float4 v[6];
    #pragma unroll
    for (int i = 0; i < 6; i++) v[i] = p[lane + 32 * i];
    float mu, inv;
    warp_stats(v, mu, inv);
    #pragma unroll
    for (int i = 0; i < 6; i++) {
        int g4 = lane + 32 * i;
        float4 s4 = sc[g4], b4 = bi[g4];
        float r[4] = {(v[i].x - mu) * inv * s4.x + b4.x,
                      (v[i].y - mu) * inv * s4.y + b4.y,
                      (v[i].z - mu) * inv * s4.z + b4.z,
                      (v[i].w - mu) * inv * s4.w + b4.w};
        #pragma unroll
        for (int c = 0; c < 4; c++) r[c] = r[c] * (1.f / (1.f + expf(-r[c])));
        if (LAST) {
            float4 xr = *reinterpret_cast<const float4*>(g_x1 + row * D_ + g4 * 4);
            float xs[4] = {xr.x, xr.y, xr.z, xr.w};
            float4 o4;
            float* po = &o4.x;
            #pragma unroll
            for (int c = 0; c < 4; c++) {
                float sum = r[c] + xs[c];
                float ax = fabsf(sum);
                po[c] = ax + log1pf(expf(-2.f * ax)) - 0.69314718055994530942f;
            }
            *reinterpret_cast<float4*>(out + row * D_ + g4 * 4) = o4;
        } else {
            __half2 h0 = __floats2half2_rn(r[0], r[1]);
            __half2 h1 = __floats2half2_rn(r[2], r[3]);
            uint2 u; u.x = *(uint32_t*)&h0; u.y = *(uint32_t*)&h1;
            *reinterpret_cast<uint2*>(g_zh + row * D_ + g4 * 4) = u;
        }
    }
}

// ---------------------------------------------------------------------------
// HMMA fp16 GEMM. Block 128x256, BK=32, 4-stage cp.async, 1 sync/iter.
//   D = A.B^T   (A [M,K] fp16 rm, B [N,K] fp16 rm, fp32 accumulate)
// 8 warps (2m x 4n), warp tile 64x64, m16n8k16.
// MODE 0: GEMM1   -> smem transpose (2 halves), scatter v into [h][b*64+k][j]
// MODE 1: circul. -> x1 = x + D (fp32 + fp16), blockIdx.z = h
// MODE 2: FFN     -> t = D + bias (fp32)
// ---------------------------------------------------------------------------
#define BM 128
#define BN 256
#define A_TILE_B  8192u            // 128x32 fp16
#define B_TILE_B  16384u           // 256x32 fp16
#define STAGE_B   (A_TILE_B + B_TILE_B)   // 24 KB
#define NSTAGE    4
#define SMEM_BYTES (NSTAGE*STAGE_B)       // 98304 (>= 66048 epi buffer)

// 64B-row swizzle: 4 chunks of 16B; chunk' = cc ^ ((row>>1)&3)
__device__ __forceinline__ uint32_t sw_off(int row, int cc) {
    return (uint32_t)(row * 64 + ((cc ^ ((row >> 1) & 3)) << 4));
}

template<int ROWS>
__device__ __forceinline__ void cp_tile(uint32_t dstBase, const __half* src,
                                        int rowBase, int kBase, int ld, int tid)
{
    const char* g = (const char*)src + ((size_t)rowBase * ld + kBase) * 2;
    #pragma unroll
    for (int t = 0; t < ROWS / 64; t++) {
        int ci = tid + t * 256;
        int row = ci >> 2, cc = ci & 3;
        CP_ASYNC(dstBase + sw_off(row, cc), g + (size_t)row * ld * 2 + cc * 16);
    }
}

template<int MODE>
__global__ void __launch_bounds__(256, 1) tc_gemm(
    const __half* __restrict__ A, const __half* __restrict__ Bm,
    int Kdim, size_t aStrZ, size_t bStrZ,
    const float* __restrict__ xin,            // mode1
    float* __restrict__ out_f,                // mode1: x1, mode2: t
    __half* __restrict__ out_h,               // mode0: vc, mode1: x1h
    const float* __restrict__ bias)           // mode2
{
    extern __shared__ char smem[];
    const int tid = threadIdx.x;
    const int wid = tid >> 5, lane = tid & 31;
    const uint32_t sbase = smem_u32(smem);

    const int mBase = blockIdx.y * BM;
    const int nBase = blockIdx.x * BN;
    const int bz = blockIdx.z;
    const __half* Ab = A  + (size_t)bz * aStrZ;
    const __half* Bb = Bm + (size_t)bz * bStrZ;

    const int warpM = wid >> 2;     // 0..1 (x64)
    const int warpN = wid & 3;      // 0..3 (x64)

    const int nc = Kdim >> 5;       // BK = 32

    #pragma unroll
    for (int s = 0; s < NSTAGE - 1; s++) {
        uint32_t sb = sbase + s * STAGE_B;
        cp_tile<BM>(sb,            Ab, mBase, s * 32, Kdim, tid);
        cp_tile<BN>(sb + A_TILE_B, Bb, nBase, s * 32, Kdim, tid);
        CP_COMMIT();
    }

    float acc[4][8][4] = {};
    const int lrow = lane & 15;     // ldmatrix source row within 16
    const int lsel = lane >> 4;     // 16B column select

    for (int c = 0; c < nc; c++) {
        CP_WAIT(NSTAGE - 2);
        __syncthreads();

        int pre = c + NSTAGE - 1;
        if (pre < nc) {
            uint32_t sb = sbase + (pre % NSTAGE) * STAGE_B;
            cp_tile<BM>(sb,            Ab, mBase, pre * 32, Kdim, tid);
            cp_tile<BN>(sb + A_TILE_B, Bb, nBase, pre * 32, Kdim, tid);
            CP_COMMIT();
        }

        uint32_t stA = sbase + (c % NSTAGE) * STAGE_B;
        uint32_t stB = stA + A_TILE_B;

        #pragma unroll
        for (int kk = 0; kk < 2; kk++) {
            int cc = kk * 2 + lsel;
            uint32_t aF[4][4], bF[4][4];
            #pragma unroll
            for (int mt = 0; mt < 4; mt++) {
                int r = warpM * 64 + mt * 16 + lrow;
                ldsm_x4(aF[mt], stA + sw_off(r, cc));
            }
            #pragma unroll
            for (int nt2 = 0; nt2 < 4; nt2++) {
                int r = warpN * 64 + nt2 * 16 + lrow;
                ldsm_x4(bF[nt2], stB + sw_off(r, cc));
            }
            #pragma unroll
            for (int mt = 0; mt < 4; mt++)
                #pragma unroll
                for (int nt = 0; nt < 8; nt++) {
                    uint32_t b0 = bF[nt >> 1][nt & 1];
                    uint32_t b1 = bF[nt >> 1][(nt & 1) + 2];
                    mma16816(acc[mt][nt], aF[mt], b0, b1);
                }
        }
    }
    CP_WAIT(0);

    const int mBaseW = mBase + warpM * 64;
    const int nBaseW = nBase + warpN * 64;

    if (MODE == 0) {
        // two 128-col halves: stage into smem [128][129], write columns
        float* sbuf = reinterpret_cast<float*>(smem);
        const int LDS = 129;
        #pragma unroll
        for (int hf = 0; hf < 2; hf++) {
            __syncthreads();
            if ((warpN >> 1) == hf) {
                #pragma unroll
                for (int mt = 0; mt < 4; mt++)
                    #pragma unroll
                    for (int nt = 0; nt < 8; nt++) {
                        int rl = warpM * 64 + mt * 16 + (lane >> 2);
                        int cl = (warpN & 1) * 64 + nt * 8 + ((lane & 3) << 1);
                        sbuf[rl * LDS + cl]           = acc[mt][nt][0];
                        sbuf[rl * LDS + cl + 1]       = acc[mt][nt][1];
                        sbuf[(rl + 8) * LDS + cl]     = acc[mt][nt][2];
                        sbuf[(rl + 8) * LDS + cl + 1] = acc[mt][nt][3];
                    }
            }
            __syncthreads();
            #pragma unroll
            for (int i = 0; i < 16; i++) {
                int cl = wid * 16 + i;
                int cg = nBase + hf * 128 + cl;
                int h = cg >> 6, k = cg & 63;
                #pragma unroll
                for (int q = 0; q < 2; q++) {
                    int m = q * 64 + lane * 2;
                    int mg = mBase + m;
                    int b = mg >> 10, j = mg & 1023;
                    size_t o = (((size_t)(h << 10) + (b << 6) + k) << 10) + j;
                    __half2 hv = __floats2half2_rn(sbuf[m * LDS + cl],
                                                   sbuf[(m + 1) * LDS + cl]);
                    *reinterpret_cast<__half2*>(out_h + o) = hv;
                }
            }
        }
    } else {
        #pragma unroll
        for (int mt = 0; mt < 4; mt++)
            #pragma unroll
            for (int nt = 0; nt < 8; nt++) {
                int i0 = mBaseW + mt * 16 + (lane >> 2);
                int cl = nBaseW + nt * 8 + ((lane & 3) << 1);
                #pragma unroll
                for (int h2 = 0; h2 < 2; h2++) {
                    int i = i0 + h2 * 8;
                    float v0 = acc[mt][nt][h2 * 2];
                    float v1 = acc[mt][nt][h2 * 2 + 1];
                    if (MODE == 1) {
                        int b = cl >> 6, k = cl & 63;
                        size_t o = ((size_t)(b << 10) + i) * D_ + bz * HS_ + k;
                        float r0 = xin[o] + v0;
                        float r1 = xin[o + 1] + v1;
                        out_f[o] = r0; out_f[o + 1] = r1;
                        *reinterpret_cast<__half2*>(out_h + o) =
                            __floats2half2_rn(r0, r1);
                    } else {
                        size_t o = (size_t)i * D_ + cl;
                        out_f[o]     = v0 + bias[cl];
                        out_f[o + 1] = v1 + bias[cl + 1];
                    }
                }
            }
    }
}

// ---------------------------------------------------------------------------
// Launch
// ---------------------------------------------------------------------------
extern "C" void kernel_launch(void* const* d_in, const int* in_sizes, int n_in,
                              void* d_out, int out_size)
{
    const float* x     = (const float*)d_in[0];
    const float* ln1_s = (const float*)d_in[1];
    const float* ln1_b = (const float*)d_in[2];
    const float* Wv    = (const float*)d_in[3];
    const float* alpha = (const float*)d_in[4];
    const float* Wf    = (const float*)d_in[5];
    const float* bf    = (const float*)d_in[6];
    const float* lnf_s = (const float*)d_in[7];
    const float* lnf_b = (const float*)d_in[8];
    float* out = (float*)d_out;

    cudaFuncSetAttribute(tc_gemm<0>, cudaFuncAttributeMaxDynamicSharedMemorySize, SMEM_BYTES);
    cudaFuncSetAttribute(tc_gemm<1>, cudaFuncAttributeMaxDynamicSharedMemorySize, SMEM_BYTES);
    cudaFuncSetAttribute(tc_gemm<2>, cudaFuncAttributeMaxDynamicSharedMemorySize, SMEM_BYTES);

    __half *xn, *wvT, *wfT, *vc, *cc, *x1h, *zh;
    float *x1, *t;
    cudaGetSymbolAddress((void**)&xn, g_xn);
    cudaGetSymbolAddress((void**)&wvT, g_wvT);
    cudaGetSymbolAddress((void**)&wfT, g_wfT);
    cudaGetSymbolAddress((void**)&vc, g_vc);
    cudaGetSymbolAddress((void**)&cc, g_cc);
    cudaGetSymbolAddress((void**)&x1h, g_x1h);
    cudaGetSymbolAddress((void**)&zh, g_zh);
    cudaGetSymbolAddress((void**)&x1, g_x1);
    cudaGetSymbolAddress((void**)&t, g_t);

    // operand prep
    conv_wvT_kernel<<<(D_*D_ + 255)/256, 256>>>(Wv);
    conv_wfT_kernel<<<(L_*D_*D_ + 255)/256, 256>>>(Wf);
    build_circ_kernel<<<H_*N_, 256>>>(alpha);
    ln1_kernel<<<M_/8, 256>>>(x, ln1_s, ln1_b);

    // GEMM1: v = xn @ Wv (scatter into circulant B layout)
    tc_gemm<0><<<dim3(D_/BN, M_/BM, 1), 256, SMEM_BYTES>>>(
        xn, wvT, D_, 0, 0, nullptr, nullptr, vc, nullptr);

    // circulant: x1 = x + C @ v (per head)
    tc_gemm<1><<<dim3(N_/BN, N_/BM, H_), 256, SMEM_BYTES>>>(
        cc, vc, N_, (size_t)N_*N_, (size_t)N_*N_, x, x1, x1h, nullptr);

    // FFN1
    tc_gemm<2><<<dim3(D_/BN, M_/BM, 1), 256, SMEM_BYTES>>>(
        x1h, wfT, D_, 0, 0, nullptr, t, nullptr, bf);
    ln_swish_kernel<0><<<M_/8, 256>>>(lnf_s, lnf_b, nullptr);

    // FFN2
    tc_gemm<2><<<dim3(D_/BN, M_/BM, 1), 256, SMEM_BYTES>>>(
        zh, wfT + (size_t)D_*D_, D_, 0, 0, nullptr, t, nullptr, bf + D_);
    ln_swish_kernel<1><<<M_/8, 256>>>(lnf_s + D_, lnf_b + D_, out);
}

// round 7
// speedup vs baseline: 4.9896x; 1.1014x over previous
#include <cuda_runtime.h>
#include <cuda_fp16.h>
#include <cstdint>

// ---------------------------------------------------------------------------
// Problem shape
// ---------------------------------------------------------------------------
#define B_  16
#define N_  1024
#define D_  768
#define H_  12
#define HS_ 64
#define M_  (B_*N_)     // 16384 token rows
#define L_  2
#define EPS_ 1e-6f

// ---------------------------------------------------------------------------
// Scratch
// ---------------------------------------------------------------------------
__device__ __half g_xn [M_*D_];        // LN1(x)           (GEMM1 A)
__device__ __half g_wvT[D_*D_];        // Wv^T [n=h*64+k][d]
__device__ __half g_wfT[L_*D_*D_];     // Wf^T [l][n][d]
__device__ __half g_vc [H_*N_*N_];     // v [h][b*64+k][j] (circ B)
__device__ __half g_cc [H_*N_*N_];     // C [h][i][j]      (circ A)
__device__ float  g_x1 [M_*D_];        // residual x + y (fp32)
__device__ __half g_x1h[M_*D_];        // fp16 copy        (FFN1 A)
__device__ __half g_th [M_*D_];        // ffn gemm out (fp16)
__device__ __half g_zh [M_*D_];        // swish(ln(t))     (FFN2 A)

// ---------------------------------------------------------------------------
// Helpers
// ---------------------------------------------------------------------------
__device__ __forceinline__ uint32_t smem_u32(const void* p) {
    uint32_t a;
    asm("{ .reg .u64 t; cvta.to.shared.u64 t, %1; cvt.u32.u64 %0, t; }"
        : "=r"(a) : "l"(p));
    return a;
}
__device__ __forceinline__ void ldsm_x4(uint32_t* d, uint32_t addr) {
    asm volatile("ldmatrix.sync.aligned.m8n8.x4.shared.b16 {%0,%1,%2,%3}, [%4];"
                 : "=r"(d[0]), "=r"(d[1]), "=r"(d[2]), "=r"(d[3]) : "r"(addr));
}
__device__ __forceinline__ void mma16816(float* d, const uint32_t* a,
                                         uint32_t b0, uint32_t b1) {
    asm volatile(
        "mma.sync.aligned.m16n8k16.row.col.f32.f16.f16.f32 "
        "{%0,%1,%2,%3}, {%4,%5,%6,%7}, {%8,%9}, {%0,%1,%2,%3};"
        : "+f"(d[0]), "+f"(d[1]), "+f"(d[2]), "+f"(d[3])
        : "r"(a[0]), "r"(a[1]), "r"(a[2]), "r"(a[3]), "r"(b0), "r"(b1));
}
#define CP_ASYNC(dst, src) \
    asm volatile("cp.async.cg.shared.global [%0], [%1], 16;" :: "r"(dst), "l"(src))
#define CP_COMMIT() asm volatile("cp.async.commit_group;" ::: "memory")
#define CP_WAIT(n)  asm volatile("cp.async.wait_group %0;" :: "n"(n) : "memory")

// ---------------------------------------------------------------------------
// Conversion kernels
// ---------------------------------------------------------------------------
__global__ void conv_wvT_kernel(const float* __restrict__ Wv) {
    int idx = blockIdx.x * blockDim.x + threadIdx.x;
    if (idx >= D_ * D_) return;
    int n = idx / D_, d = idx % D_;
    int h = n >> 6, k = n & 63;
    g_wvT[idx] = __float2half(Wv[((size_t)h * D_ + d) * HS_ + k]);
}
__global__ void conv_wfT_kernel(const float* __restrict__ Wf) {
    int idx = blockIdx.x * blockDim.x + threadIdx.x;
    if (idx >= L_ * D_ * D_) return;
    int l = idx / (D_ * D_);
    int r = idx % (D_ * D_);
    int n = r / D_, d = r % D_;
    g_wfT[idx] = __float2half(Wf[(size_t)l * D_ * D_ + (size_t)d * D_ + n]);
}
__global__ void build_circ_kernel(const float* __restrict__ alpha) {
    int bid = blockIdx.x;           // h*1024 + i
    int h = bid >> 10, i = bid & 1023;
    const float* a = alpha + (size_t)h * N_;
    size_t base = (size_t)bid * N_;
    #pragma unroll
    for (int t = 0; t < 4; t++) {
        int j = threadIdx.x + t * 256;
        g_cc[base + j] = __float2half(a[(i - j) & (N_ - 1)]);
    }
}

// ---------------------------------------------------------------------------
// Warp-per-row LayerNorm (no smem, shuffle reduction). 8 rows/block.
// ---------------------------------------------------------------------------
__device__ __forceinline__ void warp_stats(const float4* v, float& mu, float& inv) {
    float s = 0.f, q = 0.f;
    #pragma unroll
    for (int i = 0; i < 6; i++) {
        s += v[i].x + v[i].y + v[i].z + v[i].w;
        q += v[i].x*v[i].x + v[i].y*v[i].y + v[i].z*v[i].z + v[i].w*v[i].w;
    }
    #pragma unroll
    for (int o = 16; o; o >>= 1) {
        s += __shfl_xor_sync(0xffffffffu, s, o);
        q += __shfl_xor_sync(0xffffffffu, q, o);
    }
    mu = s * (1.f / D_);
    float var = q * (1.f / D_) - mu * mu;
    inv = rsqrtf(var + EPS_);
}

__global__ void __launch_bounds__(256) ln1_kernel(
    const float* __restrict__ in, const float* __restrict__ scale,
    const float* __restrict__ bias)
{
    int warp = threadIdx.x >> 5, lane = threadIdx.x & 31;
    size_t row = (size_t)blockIdx.x * 8 + warp;
    const float4* p = reinterpret_cast<const float4*>(in + row * D_);
    const float4* sc = reinterpret_cast<const float4*>(scale);
    const float4* bi = reinterpret_cast<const float4*>(bias);
    float4 v[6];
    #pragma unroll
    for (int i = 0; i < 6; i++) v[i] = p[lane + 32 * i];
    float mu, inv;
    warp_stats(v, mu, inv);
    #pragma unroll
    for (int i = 0; i < 6; i++) {
        int g4 = lane + 32 * i;
        float4 s4 = sc[g4], b4 = bi[g4];
        __half2 h0 = __floats2half2_rn((v[i].x - mu) * inv * s4.x + b4.x,
                                       (v[i].y - mu) * inv * s4.y + b4.y);
        __half2 h1 = __floats2half2_rn((v[i].z - mu) * inv * s4.z + b4.z,
                                       (v[i].w - mu) * inv * s4.w + b4.w);
        uint2 u; u.x = *(uint32_t*)&h0; u.y = *(uint32_t*)&h1;
        *reinterpret_cast<uint2*>(g_xn + row * D_ + g4 * 4) = u;
    }
}

// input t is fp16. LAST=0: z = swish(LN(t)) -> g_zh
//                  LAST=1: out = log_cosh(swish(LN(t)) + x1)
template<int LAST>
__global__ void __launch_bounds__(256) ln_swish_kernel(
    const float* __restrict__ scale, const float* __restrict__ bias,
    float* __restrict__ out)
{
    int warp = threadIdx.x >> 5, lane = threadIdx.x & 31;
    size_t row = (size_t)blockIdx.x * 8 + warp;
    const uint2* p = reinterpret_cast<const uint2*>(g_th + row * D_);
    const float4* sc = reinterpret_cast<const float4*>(scale);
    const float4* bi = reinterpret_cast<const float4*>(bias);
    float4 v[6];
    #pragma unroll
    for (int i = 0; i < 6; i++) {
        uint2 u = p[lane + 32 * i];
        __half2 h0 = *(__half2*)&u.x, h1 = *(__half2*)&u.y;
        float2 f0 = __half22float2(h0), f1 = __half22float2(h1);
        v[i] = make_float4(f0.x, f0.y, f1.x, f1.y);
    }
    float mu, inv;
    warp_stats(v, mu, inv);
    #pragma unroll
    for (int i = 0; i < 6; i++) {
        int g4 = lane + 32 * i;
        float4 s4 = sc[g4], b4 = bi[g4];
        float r[4] = {(v[i].x - mu) * inv * s4.x + b4.x,
                      (v[i].y - mu) * inv * s4.y + b4.y,
                      (v[i].z - mu) * inv * s4.z + b4.z,
                      (v[i].w - mu) * inv * s4.w + b4.w};
        #pragma unroll
        for (int c = 0; c < 4; c++) r[c] = r[c] * (1.f / (1.f + expf(-r[c])));
        if (LAST) {
            float4 xr = *reinterpret_cast<const float4*>(g_x1 + row * D_ + g4 * 4);
            float xs[4] = {xr.x, xr.y, xr.z, xr.w};
            float4 o4;
            float* po = &o4.x;
            #pragma unroll
            for (int c = 0; c < 4; c++) {
                float sum = r[c] + xs[c];
                float ax = fabsf(sum);
                po[c] = ax + log1pf(expf(-2.f * ax)) - 0.69314718055994530942f;
            }
            *reinterpret_cast<float4*>(out + row * D_ + g4 * 4) = o4;
        } else {
            __half2 h0 = __floats2half2_rn(r[0], r[1]);
            __half2 h1 = __floats2half2_rn(r[2], r[3]);
            uint2 u; u.x = *(uint32_t*)&h0; u.y = *(uint32_t*)&h1;
            *reinterpret_cast<uint2*>(g_zh + row * D_ + g4 * 4) = u;
        }
    }
}

// ---------------------------------------------------------------------------
// HMMA fp16 GEMM. Block 128x128, BK=32, 3-stage cp.async, 2 CTAs/SM.
//   D = A.B^T   (A [M,K] fp16 rm, B [N,K] fp16 rm, fp32 accumulate)
// 8 warps (2m x 4n), warp tile 64x32, m16n8k16.
// MODE 0: GEMM1   -> smem transpose (64-col chunks), scatter v [h][b*64+k][j]
// MODE 1: circul. -> x1 = x + D (fp32 + fp16), blockIdx.z = h
// MODE 2: FFN     -> t = D + bias (fp16)
// ---------------------------------------------------------------------------
#define BM 128
#define BN 128
#define TILE_B   8192u            // 128x32 fp16
#define STAGE_B  (2u*TILE_B)      // A, B
#define NSTAGE   3
#define SMEM_BYTES (NSTAGE*STAGE_B)   // 49152 ; epi buffer 33280 fits

// 64B-row swizzle: 4 chunks of 16B; chunk' = cc ^ ((row>>1)&3)
__device__ __forceinline__ uint32_t sw_off(int row, int cc) {
    return (uint32_t)(row * 64 + ((cc ^ ((row >> 1) & 3)) << 4));
}

__device__ __forceinline__ void cp_tile(uint32_t dstBase, const __half* src,
                                        int rowBase, int kBase, int ld, int tid)
{
    const char* g = (const char*)src + ((size_t)rowBase * ld + kBase) * 2;
    #pragma unroll
    for (int t = 0; t < 2; t++) {
        int ci = tid + t * 256;
        int row = ci >> 2, cc = ci & 3;
        CP_ASYNC(dstBase + sw_off(row, cc), g + (size_t)row * ld * 2 + cc * 16);
    }
}

template<int MODE>
__global__ void __launch_bounds__(256, 2) tc_gemm(
    const __half* __restrict__ A, const __half* __restrict__ Bm,
    int Kdim, size_t aStrZ, size_t bStrZ,
    const float* __restrict__ xin,            // mode1
    float* __restrict__ out_f,                // mode1: x1
    __half* __restrict__ out_h,               // mode0: vc, mode1: x1h, mode2: t
    const float* __restrict__ bias)           // mode2
{
    extern __shared__ char smem[];
    const int tid = threadIdx.x;
    const int wid = tid >> 5, lane = tid & 31;
    const uint32_t sbase = smem_u32(smem);

    const int mBase = blockIdx.y * BM;
    const int nBase = blockIdx.x * BN;
    const int bz = blockIdx.z;
    const __half* Ab = A  + (size_t)bz * aStrZ;
    const __half* Bb = Bm + (size_t)bz * bStrZ;

    const int warpM = wid >> 2;     // 0..1 (x64 rows)
    const int warpN = wid & 3;      // 0..3 (x32 cols)

    const int nc = Kdim >> 5;       // BK = 32

    #pragma unroll
    for (int s = 0; s < NSTAGE - 1; s++) {
        uint32_t sb = sbase + s * STAGE_B;
        cp_tile(sb,          Ab, mBase, s * 32, Kdim, tid);
        cp_tile(sb + TILE_B, Bb, nBase, s * 32, Kdim, tid);
        CP_COMMIT();
    }

    float acc[4][4][4] = {};
    const int lrow = lane & 15;
    const int lsel = lane >> 4;

    for (int c = 0; c < nc; c++) {
        CP_WAIT(NSTAGE - 2);
        __syncthreads();

        int pre = c + NSTAGE - 1;
        if (pre < nc) {
            uint32_t sb = sbase + (pre % NSTAGE) * STAGE_B;
            cp_tile(sb,          Ab, mBase, pre * 32, Kdim, tid);
            cp_tile(sb + TILE_B, Bb, nBase, pre * 32, Kdim, tid);
            CP_COMMIT();
        }

        uint32_t stA = sbase + (c % NSTAGE) * STAGE_B;
        uint32_t stB = stA + TILE_B;

        #pragma unroll
        for (int kk = 0; kk < 2; kk++) {
            int cc = kk * 2 + lsel;
            uint32_t aF[4][4], bF[2][4];
            #pragma unroll
            for (int mt = 0; mt < 4; mt++) {
                int r = warpM * 64 + mt * 16 + lrow;
                ldsm_x4(aF[mt], stA + sw_off(r, cc));
            }
            #pragma unroll
            for (int nt2 = 0; nt2 < 2; nt2++) {
                int r = warpN * 32 + nt2 * 16 + lrow;
                ldsm_x4(bF[nt2], stB + sw_off(r, cc));
            }
            #pragma unroll
            for (int mt = 0; mt < 4; mt++)
                #pragma unroll
                for (int nt = 0; nt < 4; nt++) {
                    uint32_t b0 = bF[nt >> 1][nt & 1];
                    uint32_t b1 = bF[nt >> 1][(nt & 1) + 2];
                    mma16816(acc[mt][nt], aF[mt], b0, b1);
                }
        }
    }
    CP_WAIT(0);

    const int mBaseW = mBase + warpM * 64;
    const int nBaseW = nBase + warpN * 32;

    if (MODE == 0) {
        // two 64-col chunks through smem [128][65], then column writes
        float* sbuf = reinterpret_cast<float*>(smem);
        const int LDS = 65;
        #pragma unroll
        for (int hf = 0; hf < 2; hf++) {
            __syncthreads();
            if ((warpN >> 1) == hf) {
                #pragma unroll
                for (int mt = 0; mt < 4; mt++)
                    #pragma unroll
                    for (int nt = 0; nt < 4; nt++) {
                        int rl = warpM * 64 + mt * 16 + (lane >> 2);
                        int cl = (warpN & 1) * 32 + nt * 8 + ((lane & 3) << 1);
                        sbuf[rl * LDS + cl]           = acc[mt][nt][0];
                        sbuf[rl * LDS + cl + 1]       = acc[mt][nt][1];
                        sbuf[(rl + 8) * LDS + cl]     = acc[mt][nt][2];
                        sbuf[(rl + 8) * LDS + cl + 1] = acc[mt][nt][3];
                    }
            }
            __syncthreads();
            #pragma unroll
            for (int i = 0; i < 8; i++) {
                int cl = wid * 8 + i;
                int cg = nBase + hf * 64 + cl;
                int h = cg >> 6, k = cg & 63;
                #pragma unroll
                for (int q = 0; q < 2; q++) {
                    int m = q * 64 + lane * 2;
                    int mg = mBase + m;
                    int b = mg >> 10, j = mg & 1023;
                    size_t o = (((size_t)(h << 10) + (b << 6) + k) << 10) + j;
                    __half2 hv = __floats2half2_rn(sbuf[m * LDS + cl],
                                                   sbuf[(m + 1) * LDS + cl]);
                    *reinterpret_cast<__half2*>(out_h + o) = hv;
                }
            }
        }
    } else {
        #pragma unroll
        for (int mt = 0; mt < 4; mt++)
            #pragma unroll
            for (int nt = 0; nt < 4; nt++) {
                int i0 = mBaseW + mt * 16 + (lane >> 2);
                int cl = nBaseW + nt * 8 + ((lane & 3) << 1);
                #pragma unroll
                for (int h2 = 0; h2 < 2; h2++) {
                    int i = i0 + h2 * 8;
                    float v0 = acc[mt][nt][h2 * 2];
                    float v1 = acc[mt][nt][h2 * 2 + 1];
                    if (MODE == 1) {
                        int b = cl >> 6, k = cl & 63;
                        size_t o = ((size_t)(b << 10) + i) * D_ + bz * HS_ + k;
                        float r0 = xin[o] + v0;
                        float r1 = xin[o + 1] + v1;
                        out_f[o] = r0; out_f[o + 1] = r1;
                        *reinterpret_cast<__half2*>(out_h + o) =
                            __floats2half2_rn(r0, r1);
                    } else {
                        size_t o = (size_t)i * D_ + cl;
                        *reinterpret_cast<__half2*>(out_h + o) =
                            __floats2half2_rn(v0 + bias[cl], v1 + bias[cl + 1]);
                    }
                }
            }
    }
}

// ---------------------------------------------------------------------------
// Launch (prep kernels forked onto a second captured stream)
// ---------------------------------------------------------------------------
extern "C" void kernel_launch(void* const* d_in, const int* in_sizes, int n_in,
                              void* d_out, int out_size)
{
    const float* x     = (const float*)d_in[0];
    const float* ln1_s = (const float*)d_in[1];
    const float* ln1_b = (const float*)d_in[2];
    const float* Wv    = (const float*)d_in[3];
    const float* alpha = (const float*)d_in[4];
    const float* Wf    = (const float*)d_in[5];
    const float* bf    = (const float*)d_in[6];
    const float* lnf_s = (const float*)d_in[7];
    const float* lnf_b = (const float*)d_in[8];
    float* out = (float*)d_out;

    static cudaStream_t s2 = nullptr;
    static cudaEvent_t ev0 = nullptr, evWv = nullptr, evCirc = nullptr, evWf = nullptr;
    if (!s2) {
        cudaStreamCreateWithFlags(&s2, cudaStreamNonBlocking);
        cudaEventCreateWithFlags(&ev0,   cudaEventDisableTiming);
        cudaEventCreateWithFlags(&evWv,  cudaEventDisableTiming);
        cudaEventCreateWithFlags(&evCirc,cudaEventDisableTiming);
        cudaEventCreateWithFlags(&evWf,  cudaEventDisableTiming);
        cudaFuncSetAttribute(tc_gemm<0>, cudaFuncAttributeMaxDynamicSharedMemorySize, SMEM_BYTES);
        cudaFuncSetAttribute(tc_gemm<1>, cudaFuncAttributeMaxDynamicSharedMemorySize, SMEM_BYTES);
        cudaFuncSetAttribute(tc_gemm<2>, cudaFuncAttributeMaxDynamicSharedMemorySize, SMEM_BYTES);
    }

    __half *xn, *wvT, *wfT, *vc, *cc, *x1h, *th, *zh;
    float *x1;
    cudaGetSymbolAddress((void**)&xn, g_xn);
    cudaGetSymbolAddress((void**)&wvT, g_wvT);
    cudaGetSymbolAddress((void**)&wfT, g_wfT);
    cudaGetSymbolAddress((void**)&vc, g_vc);
    cudaGetSymbolAddress((void**)&cc, g_cc);
    cudaGetSymbolAddress((void**)&x1h, g_x1h);
    cudaGetSymbolAddress((void**)&th, g_th);
    cudaGetSymbolAddress((void**)&zh, g_zh);
    cudaGetSymbolAddress((void**)&x1, g_x1);

    // fork: prep kernels on s2
    cudaEventRecord(ev0, 0);
    cudaStreamWaitEvent(s2, ev0, 0);
    conv_wvT_kernel<<<(D_*D_ + 255)/256, 256, 0, s2>>>(Wv);
    cudaEventRecord(evWv, s2);
    build_circ_kernel<<<H_*N_, 256, 0, s2>>>(alpha);
    cudaEventRecord(evCirc, s2);
    conv_wfT_kernel<<<(L_*D_*D_ + 255)/256, 256, 0, s2>>>(Wf);
    cudaEventRecord(evWf, s2);

    // main stream
    ln1_kernel<<<M_/8, 256>>>(x, ln1_s, ln1_b);

    cudaStreamWaitEvent(0, evWv, 0);
    tc_gemm<0><<<dim3(D_/BN, M_/BM, 1), 256, SMEM_BYTES>>>(
        xn, wvT, D_, 0, 0, nullptr, nullptr, vc, nullptr);

    cudaStreamWaitEvent(0, evCirc, 0);
    tc_gemm<1><<<dim3(N_/BN, N_/BM, H_), 256, SMEM_BYTES>>>(
        cc, vc, N_, (size_t)N_*N_, (size_t)N_*N_, x, x1, x1h, nullptr);

    cudaStreamWaitEvent(0, evWf, 0);
    tc_gemm<2><<<dim3(D_/BN, M_/BM, 1), 256, SMEM_BYTES>>>(
        x1h, wfT, D_, 0, 0, nullptr, nullptr, th, bf);
    ln_swish_kernel<0><<<M_/8, 256>>>(lnf_s, lnf_b, nullptr);

    tc_gemm<2><<<dim3(D_/BN, M_/BM, 1), 256, SMEM_BYTES>>>(
        zh, wfT + (size_t)D_*D_, D_, 0, 0, nullptr, nullptr, th, bf + D_);
    ln_swish_kernel<1><<<M_/8, 256>>>(lnf_s + D_, lnf_b + D_, out);
}